// round 9
// baseline (speedup 1.0000x reference)
#include <cuda_runtime.h>
#include <cuda_fp16.h>
#include <cstdint>
#include <math.h>

// ---------------------------------------------------------------------------
// Fixed problem: B=4, S=2048, D=DK=1024. M = B*S = 8192.
// R9: fp16 HMMA, CTA 128x128 with 4 warps (2x2), warp tile 64x64,
// 128 threads/CTA, 2 CTA/SM, ~190 regs/thread. ldsm traffic -33%.
// Softmax folded as in R7 (E fp16 unnormalized, inv in AV epilogue).
// ---------------------------------------------------------------------------
#define BATCH 4
#define SEQ   2048
#define DIM   1024
#define DKV   1024
#define MTOT  (BATCH * SEQ)

#define TILE  128
#define KC    64          // fp16 elements per K-chunk (128B rows, SW128)
#define NTHR  128

// ---------------- scratch (device globals; no allocation) -------------------
__device__ __half g_x16[(size_t)MTOT * DIM];
__device__ __half g_wt16[3][(size_t)DIM * DKV];          // W^T (contiguous)
__device__ __half g_q16[(size_t)MTOT * DKV];
__device__ __half g_k16[(size_t)MTOT * DKV];
__device__ __half g_vt16[(size_t)MTOT * DKV];            // [B][DKV][SEQ]
__device__ __half g_E [(size_t)BATCH * SEQ * SEQ];       // exp(scores), fp16
__device__ float  g_rsum[(size_t)MTOT * 16];
__device__ float  g_inv [(size_t)MTOT];

// ---------------- PTX helpers ----------------------------------------------
static __device__ __forceinline__ uint32_t smem_u32(const void* p) {
    uint32_t a;
    asm("{ .reg .u64 t; cvta.to.shared.u64 t, %1; cvt.u32.u64 %0, t; }" : "=r"(a) : "l"(p));
    return a;
}
static __device__ __forceinline__ void cp16(uint32_t dst, const void* src) {
    asm volatile("cp.async.cg.shared.global [%0], [%1], 16;" :: "r"(dst), "l"(src) : "memory");
}
static __device__ __forceinline__ void cp_commit() {
    asm volatile("cp.async.commit_group;" ::: "memory");
}
static __device__ __forceinline__ void ldsm4(uint32_t* r, uint32_t addr) {
    asm volatile("ldmatrix.sync.aligned.m8n8.x4.shared.b16 {%0,%1,%2,%3}, [%4];"
                 : "=r"(r[0]), "=r"(r[1]), "=r"(r[2]), "=r"(r[3]) : "r"(addr));
}
static __device__ __forceinline__ void mma16816(float* c, const uint32_t* a, const uint32_t* b) {
    asm volatile(
        "mma.sync.aligned.m16n8k16.row.col.f32.f16.f16.f32 "
        "{%0,%1,%2,%3}, {%4,%5,%6,%7}, {%8,%9}, {%0,%1,%2,%3};"
        : "+f"(c[0]), "+f"(c[1]), "+f"(c[2]), "+f"(c[3])
        : "r"(a[0]), "r"(a[1]), "r"(a[2]), "r"(a[3]), "r"(b[0]), "r"(b[1]));
}
static __device__ __forceinline__ uint32_t sw128(uint32_t off) {
    return off ^ ((off >> 3) & 0x70);
}

// Stage (32KB): A @0 (16KB), B @16KB. 128 rows x 128B, SW128 swizzle.
#define STAGE_BYTES 32768
#define NSTAGE      3
#define SMEM_BYTES  (1024 + NSTAGE * STAGE_BYTES)

static __device__ __forceinline__ void load_chunk(
    const __half* A, const __half* B, int K,
    int m0, int n0, int koff, uint32_t stage, int tid)
{
    #pragma unroll
    for (int j = 0; j < 8; j++) {
        int id = tid + j * NTHR;                // 0..1023
        int r  = id >> 3;                       // 0..127
        int cb = (id & 7) << 4;                 // byte col in 128B row
        uint32_t sw = sw128((uint32_t)((r << 7) + cb));
        cp16(stage +         sw, A + (long)(m0 + r) * K + koff + (cb >> 1));
        cp16(stage + 16384 + sw, B + (long)(n0 + r) * K + koff + (cb >> 1));
    }
    cp_commit();
}

// Shared prolog + mainloop + accumulator->tile spill.
// 4 warps in 2x2; warp tile 64x64; acc[4][8][4] = 128 fp32/thread.
#define GEMM_BODY(Aptr, Bptr, Kdim)                                              \
    extern __shared__ char smraw[];                                              \
    const int tid = threadIdx.x;                                                 \
    const int wid = tid >> 5;                                                    \
    const int lid = tid & 31;                                                    \
    const int z   = blockIdx.z;                                                  \
    const int m0  = blockIdx.y * TILE;                                           \
    const int n0  = blockIdx.x * TILE;                                           \
    const uint32_t smb = (smem_u32(smraw) + 1023u) & ~1023u;                     \
    uint32_t stg[NSTAGE];                                                        \
    _Pragma("unroll")                                                            \
    for (int s = 0; s < NSTAGE; s++) stg[s] = smb + s * STAGE_BYTES;             \
    const int wm = (wid >> 1) * 64;                                              \
    const int wn = (wid & 1) * 64;                                               \
    const int aRow  = wm + (lid & 15);                                           \
    const int aColB = (lid >> 4) << 4;                                           \
    const int bRow  = wn + (((lid >> 4) & 1) << 3) + (lid & 7);                  \
    const int bColB = ((lid >> 3) & 1) << 4;                                     \
    uint32_t aOff[4], bOff[4];                                                   \
    _Pragma("unroll")                                                            \
    for (int t = 0; t < 4; t++) {                                                \
        aOff[t] = sw128((uint32_t)((aRow + t * 16) << 7) + aColB);               \
        bOff[t] = sw128((uint32_t)((bRow + t * 16) << 7) + bColB) + 16384;       \
    }                                                                            \
    float acc[4][8][4];                                                          \
    _Pragma("unroll")                                                            \
    for (int mi = 0; mi < 4; mi++)                                               \
        _Pragma("unroll")                                                        \
        for (int ni = 0; ni < 8; ni++)                                           \
            _Pragma("unroll")                                                    \
            for (int r = 0; r < 4; r++) acc[mi][ni][r] = 0.0f;                   \
    const int NC = (Kdim) / KC;                                                  \
    load_chunk((Aptr), (Bptr), (Kdim), m0, n0, 0, stg[0], tid);                  \
    load_chunk((Aptr), (Bptr), (Kdim), m0, n0, KC, stg[1], tid);                 \
    uint32_t cur = stg[0];                                                       \
    int nxt = 2;                                                                 \
    for (int i = 0; i < NC; i++) {                                               \
        asm volatile("cp.async.wait_group 1;" ::: "memory");                     \
        __syncthreads();                                                         \
        if (i + 2 < NC)                                                          \
            load_chunk((Aptr), (Bptr), (Kdim), m0, n0, (i + 2) * KC, stg[nxt], tid); \
        else                                                                     \
            cp_commit();                                                         \
        _Pragma("unroll")                                                        \
        for (int kk = 0; kk < 4; kk++) {                                         \
            const uint32_t x_ = (uint32_t)(kk << 5);                             \
            uint32_t fa[4][4], fb[4][4];                                         \
            _Pragma("unroll")                                                    \
            for (int t = 0; t < 4; t++) ldsm4(fb[t], cur + (bOff[t] ^ x_));      \
            _Pragma("unroll")                                                    \
            for (int t = 0; t < 4; t++) ldsm4(fa[t], cur + (aOff[t] ^ x_));      \
            _Pragma("unroll")                                                    \
            for (int mi = 0; mi < 4; mi++)                                       \
                _Pragma("unroll")                                                \
                for (int nf = 0; nf < 4; nf++) {                                 \
                    mma16816(acc[mi][nf * 2],     fa[mi], &fb[nf][0]);           \
                    mma16816(acc[mi][nf * 2 + 1], fa[mi], &fb[nf][2]);           \
                }                                                                \
        }                                                                        \
        cur = stg[(i + 1) % NSTAGE];                                             \
        nxt = (nxt + 1) % NSTAGE;                                                \
    }                                                                            \
    __syncthreads();                                                             \
    float* tile = (float*)(smraw + (smb - smem_u32(smraw)));                     \
    {                                                                            \
        const int r0 = lid >> 2;                                                 \
        const int c0 = (lid & 3) * 2;                                            \
        _Pragma("unroll")                                                        \
        for (int mi = 0; mi < 4; mi++)                                           \
            _Pragma("unroll")                                                    \
            for (int ni = 0; ni < 8; ni++) {                                     \
                int m = wm + mi * 16 + r0;                                       \
                int n = wn + ni * 8 + c0;                                        \
                tile[m * 129 + n]           = acc[mi][ni][0];                    \
                tile[m * 129 + n + 1]       = acc[mi][ni][1];                    \
                tile[(m + 8) * 129 + n]     = acc[mi][ni][2];                    \
                tile[(m + 8) * 129 + n + 1] = acc[mi][ni][3];                    \
            }                                                                    \
    }                                                                            \
    __syncthreads();

// ---------------- merged projection GEMM: z = 0(Q), 1(K), 2(V) --------------
__global__ void __launch_bounds__(NTHR, 2)
gemm_proj(const __half* __restrict__ A, const __half* __restrict__ Wt,
          const float* __restrict__ b0, const float* __restrict__ b1,
          const float* __restrict__ b2,
          __half* __restrict__ o0, __half* __restrict__ o1,
          __half* __restrict__ o2)
{
    GEMM_BODY(A, Wt + (long)blockIdx.z * DIM * DKV, DIM)

    const float* bias = (z == 0) ? b0 : (z == 1) ? b1 : b2;
    if (z < 2) {
        __half* dst = (z == 0) ? o0 : o1;
        for (int idx = tid; idx < TILE * TILE; idx += NTHR) {
            int r = idx >> 7, c = idx & 127;
            float v = tile[r * 129 + c] + bias[n0 + c];
            dst[(long)(m0 + r) * DKV + n0 + c] = __float2half(v);
        }
    } else {
        // V: write transposed Vt[b][n][seq]
        const int b = m0 >> 11, seq0 = m0 & 2047;
        for (int idx = tid; idx < TILE * TILE; idx += NTHR) {
            int n = idx >> 7, mm = idx & 127;
            float v = tile[mm * 129 + n] + bias[n0 + n];
            o2[(long)b * DKV * SEQ + (long)(n0 + n) * SEQ + seq0 + mm] = __float2half(v);
        }
    }
}

// ---------------- scores GEMM: E = exp(QK^T/32 + mask) fp16 + rowsums -------
__global__ void __launch_bounds__(NTHR, 2)
gemm_scores(const __half* __restrict__ Q, const __half* __restrict__ Km,
            const float* __restrict__ mask, __half* __restrict__ Eh,
            float* __restrict__ rsum)
{
    GEMM_BODY(Q + (long)blockIdx.z * SEQ * DKV,
              Km + (long)blockIdx.z * SEQ * DKV, DKV)

    const long bo = (long)z * SEQ * SEQ;
    for (int idx = tid; idx < TILE * TILE; idx += NTHR) {
        int r = idx >> 7, c = idx & 127;
        long o = bo + (long)(m0 + r) * SEQ + n0 + c;
        float e = __expf(tile[r * 129 + c] * 0.03125f + mask[o]);
        tile[r * 129 + c] = e;
        Eh[o] = __float2half(e);
    }
    __syncthreads();
    {
        float s = 0.0f;
        #pragma unroll 8
        for (int c = 0; c < 128; c++) s += tile[tid * 129 + c];
        rsum[((long)(z << 11) + m0 + tid) * 16 + blockIdx.x] = s;
    }
}

// ---------------- AV GEMM: out = inv[row] * (E @ V) -------------------------
__global__ void __launch_bounds__(NTHR, 2)
gemm_av(const __half* __restrict__ E, const __half* __restrict__ Vt,
        const float* __restrict__ inv, float* __restrict__ outF)
{
    GEMM_BODY(E + (long)blockIdx.z * SEQ * SEQ,
              Vt + (long)blockIdx.z * DKV * SEQ, SEQ)

    const long bo = (long)z * SEQ * DKV;
    for (int idx = tid; idx < TILE * TILE; idx += NTHR) {
        int r = idx >> 7, c = idx & 127;
        float iv = inv[(z << 11) + m0 + r];
        outF[bo + (long)(m0 + r) * DKV + n0 + c] = tile[r * 129 + c] * iv;
    }
}

// ---------------- 1/rowsum reduce -------------------------------------------
__global__ void __launch_bounds__(256)
inv_rows(const float* __restrict__ rsum, float* __restrict__ inv)
{
    int R = blockIdx.x * 256 + threadIdx.x;
    float s = 0.0f;
    #pragma unroll
    for (int t = 0; t < 16; t++) s += rsum[(long)R * 16 + t];
    inv[R] = 1.0f / s;
}

// ---------------- x -> fp16 --------------------------------------------------
__global__ void __launch_bounds__(256)
conv_x(const float4* __restrict__ in, __half2* __restrict__ out, int n4)
{
    int i = blockIdx.x * 256 + threadIdx.x;
    if (i >= n4) return;
    float4 v = in[i];
    out[i * 2]     = __floats2half2_rn(v.x, v.y);
    out[i * 2 + 1] = __floats2half2_rn(v.z, v.w);
}

// ---------------- transpose + convert W (z = 0,1,2 merged) ------------------
__global__ void __launch_bounds__(256)
tconv_w(const float* __restrict__ W0, const float* __restrict__ W1,
        const float* __restrict__ W2, __half* __restrict__ out)
{
    __shared__ float t[32][33];
    const int zz = blockIdx.z;
    const float* in = (zz == 0) ? W0 : (zz == 1) ? W1 : W2;
    __half* o = out + (long)zz * DIM * DKV;
    const int bx = blockIdx.x * 32, by = blockIdx.y * 32;
    const int tx = threadIdx.x, ty = threadIdx.y;       // block (32,8)
    #pragma unroll
    for (int k = 0; k < 32; k += 8)
        t[ty + k][tx] = in[(long)(by + ty + k) * DKV + bx + tx];
    __syncthreads();
    #pragma unroll
    for (int k = 0; k < 32; k += 8)
        o[(long)(bx + ty + k) * DIM + by + tx] = __float2half(t[tx][ty + k]);
}

// ---------------------------------------------------------------------------
extern "C" void kernel_launch(void* const* d_in, const int* in_sizes, int n_in,
                              void* d_out, int out_size)
{
    const float* x    = (const float*)d_in[0];
    const float* mask = (const float*)d_in[1];
    const float* Wq   = (const float*)d_in[2];
    const float* bq   = (const float*)d_in[3];
    const float* Wk   = (const float*)d_in[4];
    const float* bk   = (const float*)d_in[5];
    const float* Wv   = (const float*)d_in[6];
    const float* bv   = (const float*)d_in[7];
    float* out = (float*)d_out;

    __half *x16, *wt16, *q16, *k16, *vt16, *Ep;
    float *rsp, *ivp;
    cudaGetSymbolAddress((void**)&x16,  g_x16);
    cudaGetSymbolAddress((void**)&wt16, g_wt16);
    cudaGetSymbolAddress((void**)&q16,  g_q16);
    cudaGetSymbolAddress((void**)&k16,  g_k16);
    cudaGetSymbolAddress((void**)&vt16, g_vt16);
    cudaGetSymbolAddress((void**)&Ep,   g_E);
    cudaGetSymbolAddress((void**)&rsp,  g_rsum);
    cudaGetSymbolAddress((void**)&ivp,  g_inv);

    cudaFuncSetAttribute(gemm_proj,   cudaFuncAttributeMaxDynamicSharedMemorySize, SMEM_BYTES);
    cudaFuncSetAttribute(gemm_scores, cudaFuncAttributeMaxDynamicSharedMemorySize, SMEM_BYTES);
    cudaFuncSetAttribute(gemm_av,     cudaFuncAttributeMaxDynamicSharedMemorySize, SMEM_BYTES);

    // 1) convert x; transpose+convert all W's (one launch)
    {
        int n4 = MTOT * DIM / 4;
        conv_x<<<n4 / 256, 256>>>((const float4*)x, (__half2*)x16, n4);
        dim3 tb(32, 8), tg(32, 32, 3);
        tconv_w<<<tg, tb>>>(Wq, Wk, Wv, wt16);
    }

    dim3 blk(NTHR);

    // 2) Q/K/V projections in one launch (z = 0,1,2)
    {
        dim3 g(DKV / TILE, MTOT / TILE, 3);
        gemm_proj<<<g, blk, SMEM_BYTES>>>(x16, wt16, bq, bk, bv, q16, k16, vt16);
    }

    // 3) E = exp(Q K^T / 32 + mask) fp16, per-tile row sums   (per batch)
    {
        dim3 g(SEQ / TILE, SEQ / TILE, BATCH);
        gemm_scores<<<g, blk, SMEM_BYTES>>>(q16, k16, mask, Ep, rsp);
    }

    // 4) inv[row] = 1 / rowsum
    inv_rows<<<MTOT / 256, 256>>>(rsp, ivp);

    // 5) out = inv * (E @ V)
    {
        dim3 g(DKV / TILE, SEQ / TILE, BATCH);
        gemm_av<<<g, blk, SMEM_BYTES>>>(Ep, vt16, ivp, out);
    }
}

// round 10
// speedup vs baseline: 1.0519x; 1.0519x over previous
#include <cuda_runtime.h>
#include <cuda_fp16.h>
#include <cstdint>
#include <math.h>

// ---------------------------------------------------------------------------
// Fixed problem: B=4, S=2048, D=DK=1024. M = B*S = 8192.
// R10: R8 GEMM config (128x128, 8 warps 2x4, 2 CTA/SM) + hybrid exp in the
// scores epilogue: 1/3 of exponentials on FFMA pipe (poly), 2/3 on MUFU.
// Softmax normalization folded into AV epilogue; E stored fp16 unnormalized.
// ---------------------------------------------------------------------------
#define BATCH 4
#define SEQ   2048
#define DIM   1024
#define DKV   1024
#define MTOT  (BATCH * SEQ)

#define TILE  128
#define KC    64          // fp16 elements per K-chunk (128B rows, SW128)

// ---------------- scratch (device globals; no allocation) -------------------
__device__ __half g_x16[(size_t)MTOT * DIM];
__device__ __half g_wt16[3][(size_t)DIM * DKV];          // W^T (contiguous)
__device__ __half g_q16[(size_t)MTOT * DKV];
__device__ __half g_k16[(size_t)MTOT * DKV];
__device__ __half g_vt16[(size_t)MTOT * DKV];            // [B][DKV][SEQ]
__device__ __half g_E [(size_t)BATCH * SEQ * SEQ];       // exp(scores), fp16
__device__ float  g_rsum[(size_t)MTOT * 16];
__device__ float  g_inv [(size_t)MTOT];

// ---------------- PTX helpers ----------------------------------------------
static __device__ __forceinline__ uint32_t smem_u32(const void* p) {
    uint32_t a;
    asm("{ .reg .u64 t; cvta.to.shared.u64 t, %1; cvt.u32.u64 %0, t; }" : "=r"(a) : "l"(p));
    return a;
}
static __device__ __forceinline__ void cp16(uint32_t dst, const void* src) {
    asm volatile("cp.async.cg.shared.global [%0], [%1], 16;" :: "r"(dst), "l"(src) : "memory");
}
static __device__ __forceinline__ void cp_commit() {
    asm volatile("cp.async.commit_group;" ::: "memory");
}
static __device__ __forceinline__ void ldsm4(uint32_t* r, uint32_t addr) {
    asm volatile("ldmatrix.sync.aligned.m8n8.x4.shared.b16 {%0,%1,%2,%3}, [%4];"
                 : "=r"(r[0]), "=r"(r[1]), "=r"(r[2]), "=r"(r[3]) : "r"(addr));
}
static __device__ __forceinline__ void mma16816(float* c, const uint32_t* a, const uint32_t* b) {
    asm volatile(
        "mma.sync.aligned.m16n8k16.row.col.f32.f16.f16.f32 "
        "{%0,%1,%2,%3}, {%4,%5,%6,%7}, {%8,%9}, {%0,%1,%2,%3};"
        : "+f"(c[0]), "+f"(c[1]), "+f"(c[2]), "+f"(c[3])
        : "r"(a[0]), "r"(a[1]), "r"(a[2]), "r"(a[3]), "r"(b[0]), "r"(b[1]));
}
static __device__ __forceinline__ uint32_t sw128(uint32_t off) {
    return off ^ ((off >> 3) & 0x70);
}
// exp on the FFMA pipe: e^x = 2^(x*log2e), magic-constant rounding +
// degree-4 Taylor of 2^f on [-0.5, 0.5] (rel err ~4e-5).
static __device__ __forceinline__ float fexp_poly(float x) {
    float y = fmaxf(x, -80.0f) * 1.4426950408889634f;
    float r = y + 12582912.0f;              // 1.5*2^23: round-to-nearest-int
    float f = y - (r - 12582912.0f);        // frac in [-0.5, 0.5]
    float p =             1.3333558e-3f;
    p = __fmaf_rn(p, f,   9.6181291e-3f);
    p = __fmaf_rn(p, f,   5.5504109e-2f);
    p = __fmaf_rn(p, f,   2.4022651e-1f);
    p = __fmaf_rn(p, f,   6.9314718e-1f);
    p = __fmaf_rn(p, f,   1.0f);
    return __int_as_float(__float_as_int(p) + (__float_as_int(r) << 23));
}

// Stage (32KB): A @0 (16KB), B @16KB. 128 rows x 128B, SW128 swizzle.
#define STAGE_BYTES 32768
#define NSTAGE      3
#define SMEM_BYTES  (1024 + NSTAGE * STAGE_BYTES)

static __device__ __forceinline__ void load_chunk(
    const __half* A, const __half* B, int K,
    int m0, int n0, int koff, uint32_t stage, int tid)
{
    #pragma unroll
    for (int j = 0; j < 4; j++) {
        int id = tid + j * 256;                 // 0..1023
        int r  = id >> 3;                       // 0..127
        int cb = (id & 7) << 4;                 // byte col in 128B row
        uint32_t sw = sw128((uint32_t)((r << 7) + cb));
        cp16(stage +         sw, A + (long)(m0 + r) * K + koff + (cb >> 1));
        cp16(stage + 16384 + sw, B + (long)(n0 + r) * K + koff + (cb >> 1));
    }
    cp_commit();
}

// Shared prolog + mainloop + accumulator->tile spill (R8 config: 2x4 warps)
#define GEMM_BODY(Aptr, Bptr, Kdim)                                              \
    extern __shared__ char smraw[];                                              \
    const int tid = threadIdx.x;                                                 \
    const int wid = tid >> 5;                                                    \
    const int lid = tid & 31;                                                    \
    const int z   = blockIdx.z;                                                  \
    const int m0  = blockIdx.y * TILE;                                           \
    const int n0  = blockIdx.x * TILE;                                           \
    const uint32_t smb = (smem_u32(smraw) + 1023u) & ~1023u;                     \
    uint32_t stg[NSTAGE];                                                        \
    _Pragma("unroll")                                                            \
    for (int s = 0; s < NSTAGE; s++) stg[s] = smb + s * STAGE_BYTES;             \
    const int wm = (wid >> 2) * 64;                                              \
    const int wn = (wid & 3) * 32;                                               \
    const int aRow  = wm + (lid & 15);                                           \
    const int aColB = (lid >> 4) << 4;                                           \
    const int bRow  = wn + (((lid >> 4) & 1) << 3) + (lid & 7);                  \
    const int bColB = ((lid >> 3) & 1) << 4;                                     \
    uint32_t aOff[4], bOff[2];                                                   \
    _Pragma("unroll")                                                            \
    for (int t = 0; t < 4; t++)                                                  \
        aOff[t] = sw128((uint32_t)((aRow + t * 16) << 7) + aColB);               \
    _Pragma("unroll")                                                            \
    for (int t = 0; t < 2; t++)                                                  \
        bOff[t] = sw128((uint32_t)((bRow + t * 16) << 7) + bColB) + 16384;       \
    float acc[4][4][4];                                                          \
    _Pragma("unroll")                                                            \
    for (int mi = 0; mi < 4; mi++)                                               \
        _Pragma("unroll")                                                        \
        for (int ni = 0; ni < 4; ni++)                                           \
            _Pragma("unroll")                                                    \
            for (int r = 0; r < 4; r++) acc[mi][ni][r] = 0.0f;                   \
    const int NC = (Kdim) / KC;                                                  \
    load_chunk((Aptr), (Bptr), (Kdim), m0, n0, 0, stg[0], tid);                  \
    load_chunk((Aptr), (Bptr), (Kdim), m0, n0, KC, stg[1], tid);                 \
    uint32_t cur = stg[0];                                                       \
    int nxt = 2;                                                                 \
    for (int i = 0; i < NC; i++) {                                               \
        asm volatile("cp.async.wait_group 1;" ::: "memory");                     \
        __syncthreads();                                                         \
        if (i + 2 < NC)                                                          \
            load_chunk((Aptr), (Bptr), (Kdim), m0, n0, (i + 2) * KC, stg[nxt], tid); \
        else                                                                     \
            cp_commit();                                                         \
        _Pragma("unroll")                                                        \
        for (int kk = 0; kk < 4; kk++) {                                         \
            const uint32_t x_ = (uint32_t)(kk << 5);                             \
            uint32_t fb[2][4];                                                   \
            _Pragma("unroll")                                                    \
            for (int t = 0; t < 2; t++) ldsm4(fb[t], cur + (bOff[t] ^ x_));      \
            _Pragma("unroll")                                                    \
            for (int mi = 0; mi < 4; mi++) {                                     \
                uint32_t fa[4];                                                  \
                ldsm4(fa, cur + (aOff[mi] ^ x_));                                \
                _Pragma("unroll")                                                \
                for (int ni = 0; ni < 4; ni++)                                   \
                    mma16816(acc[mi][ni], fa, &fb[ni >> 1][(ni & 1) * 2]);       \
            }                                                                    \
        }                                                                        \
        cur = stg[(i + 1) % NSTAGE];                                             \
        nxt = (nxt + 1) % NSTAGE;                                                \
    }                                                                            \
    __syncthreads();                                                             \
    float* tile = (float*)(smraw + (smb - smem_u32(smraw)));                     \
    {                                                                            \
        const int r0 = lid >> 2;                                                 \
        const int c0 = (lid & 3) * 2;                                            \
        _Pragma("unroll")                                                        \
        for (int mi = 0; mi < 4; mi++)                                           \
            _Pragma("unroll")                                                    \
            for (int ni = 0; ni < 4; ni++) {                                     \
                int m = wm + mi * 16 + r0;                                       \
                int n = wn + ni * 8 + c0;                                        \
                tile[m * 129 + n]           = acc[mi][ni][0];                    \
                tile[m * 129 + n + 1]       = acc[mi][ni][1];                    \
                tile[(m + 8) * 129 + n]     = acc[mi][ni][2];                    \
                tile[(m + 8) * 129 + n + 1] = acc[mi][ni][3];                    \
            }                                                                    \
    }                                                                            \
    __syncthreads();

// ---------------- merged projection GEMM: z = 0(Q), 1(K), 2(V) --------------
__global__ void __launch_bounds__(256, 2)
gemm_proj(const __half* __restrict__ A, const __half* __restrict__ Wt,
          const float* __restrict__ b0, const float* __restrict__ b1,
          const float* __restrict__ b2,
          __half* __restrict__ o0, __half* __restrict__ o1,
          __half* __restrict__ o2)
{
    GEMM_BODY(A, Wt + (long)blockIdx.z * DIM * DKV, DIM)

    const float* bias = (z == 0) ? b0 : (z == 1) ? b1 : b2;
    if (z < 2) {
        __half* dst = (z == 0) ? o0 : o1;
        for (int idx = tid; idx < TILE * TILE; idx += 256) {
            int r = idx >> 7, c = idx & 127;
            float v = tile[r * 129 + c] + bias[n0 + c];
            dst[(long)(m0 + r) * DKV + n0 + c] = __float2half(v);
        }
    } else {
        // V: write transposed Vt[b][n][seq]
        const int b = m0 >> 11, seq0 = m0 & 2047;
        for (int idx = tid; idx < TILE * TILE; idx += 256) {
            int n = idx >> 7, mm = idx & 127;
            float v = tile[mm * 129 + n] + bias[n0 + n];
            o2[(long)b * DKV * SEQ + (long)(n0 + n) * SEQ + seq0 + mm] = __float2half(v);
        }
    }
}

// ---------------- scores GEMM: E = exp(QK^T/32 + mask) fp16 + rowsums -------
// Hybrid exp: every 3rd iteration uses the FFMA-pipe poly, others MUFU.
__global__ void __launch_bounds__(256, 2)
gemm_scores(const __half* __restrict__ Q, const __half* __restrict__ Km,
            const float* __restrict__ mask, __half* __restrict__ Eh,
            float* __restrict__ rsum)
{
    GEMM_BODY(Q + (long)blockIdx.z * SEQ * DKV,
              Km + (long)blockIdx.z * SEQ * DKV, DKV)

    const long bo = (long)z * SEQ * SEQ;
    #pragma unroll
    for (int j = 0; j < 64; j++) {
        int idx = tid + j * 256;
        int r = idx >> 7, c = idx & 127;
        long o = bo + (long)(m0 + r) * SEQ + n0 + c;
        float v = __fmaf_rn(tile[r * 129 + c], 0.03125f, mask[o]);
        float e = ((j % 3) == 0) ? fexp_poly(v) : __expf(v);
        __half eh = __float2half(e);
        Eh[o] = eh;
        // rowsum over the fp16-rounded values so numerator/denominator
        // quantization cancels in the final softmax ratio
        tile[r * 129 + c] = __half2float(eh);
    }
    __syncthreads();
    if (tid < 128) {
        float s = 0.0f;
        #pragma unroll 8
        for (int c = 0; c < 128; c++) s += tile[tid * 129 + c];
        rsum[((long)(z << 11) + m0 + tid) * 16 + blockIdx.x] = s;
    }
}

// ---------------- AV GEMM: out = inv[row] * (E @ V) -------------------------
__global__ void __launch_bounds__(256, 2)
gemm_av(const __half* __restrict__ E, const __half* __restrict__ Vt,
        const float* __restrict__ inv, float* __restrict__ outF)
{
    GEMM_BODY(E + (long)blockIdx.z * SEQ * SEQ,
              Vt + (long)blockIdx.z * DKV * SEQ, SEQ)

    const long bo = (long)z * SEQ * DKV;
    for (int idx = tid; idx < TILE * TILE; idx += 256) {
        int r = idx >> 7, c = idx & 127;
        float iv = inv[(z << 11) + m0 + r];
        outF[bo + (long)(m0 + r) * DKV + n0 + c] = tile[r * 129 + c] * iv;
    }
}

// ---------------- 1/rowsum reduce -------------------------------------------
__global__ void __launch_bounds__(256)
inv_rows(const float* __restrict__ rsum, float* __restrict__ inv)
{
    int R = blockIdx.x * 256 + threadIdx.x;
    float s = 0.0f;
    #pragma unroll
    for (int t = 0; t < 16; t++) s += rsum[(long)R * 16 + t];
    inv[R] = 1.0f / s;
}

// ---------------- x -> fp16 --------------------------------------------------
__global__ void __launch_bounds__(256)
conv_x(const float4* __restrict__ in, __half2* __restrict__ out, int n4)
{
    int i = blockIdx.x * 256 + threadIdx.x;
    if (i >= n4) return;
    float4 v = in[i];
    out[i * 2]     = __floats2half2_rn(v.x, v.y);
    out[i * 2 + 1] = __floats2half2_rn(v.z, v.w);
}

// ---------------- transpose + convert W (z = 0,1,2 merged) ------------------
__global__ void __launch_bounds__(256)
tconv_w(const float* __restrict__ W0, const float* __restrict__ W1,
        const float* __restrict__ W2, __half* __restrict__ out)
{
    __shared__ float t[32][33];
    const int zz = blockIdx.z;
    const float* in = (zz == 0) ? W0 : (zz == 1) ? W1 : W2;
    __half* o = out + (long)zz * DIM * DKV;
    const int bx = blockIdx.x * 32, by = blockIdx.y * 32;
    const int tx = threadIdx.x, ty = threadIdx.y;       // block (32,8)
    #pragma unroll
    for (int k = 0; k < 32; k += 8)
        t[ty + k][tx] = in[(long)(by + ty + k) * DKV + bx + tx];
    __syncthreads();
    #pragma unroll
    for (int k = 0; k < 32; k += 8)
        o[(long)(bx + ty + k) * DIM + by + tx] = __float2half(t[tx][ty + k]);
}

// ---------------------------------------------------------------------------
extern "C" void kernel_launch(void* const* d_in, const int* in_sizes, int n_in,
                              void* d_out, int out_size)
{
    const float* x    = (const float*)d_in[0];
    const float* mask = (const float*)d_in[1];
    const float* Wq   = (const float*)d_in[2];
    const float* bq   = (const float*)d_in[3];
    const float* Wk   = (const float*)d_in[4];
    const float* bk   = (const float*)d_in[5];
    const float* Wv   = (const float*)d_in[6];
    const float* bv   = (const float*)d_in[7];
    float* out = (float*)d_out;

    __half *x16, *wt16, *q16, *k16, *vt16, *Ep;
    float *rsp, *ivp;
    cudaGetSymbolAddress((void**)&x16,  g_x16);
    cudaGetSymbolAddress((void**)&wt16, g_wt16);
    cudaGetSymbolAddress((void**)&q16,  g_q16);
    cudaGetSymbolAddress((void**)&k16,  g_k16);
    cudaGetSymbolAddress((void**)&vt16, g_vt16);
    cudaGetSymbolAddress((void**)&Ep,   g_E);
    cudaGetSymbolAddress((void**)&rsp,  g_rsum);
    cudaGetSymbolAddress((void**)&ivp,  g_inv);

    cudaFuncSetAttribute(gemm_proj,   cudaFuncAttributeMaxDynamicSharedMemorySize, SMEM_BYTES);
    cudaFuncSetAttribute(gemm_scores, cudaFuncAttributeMaxDynamicSharedMemorySize, SMEM_BYTES);
    cudaFuncSetAttribute(gemm_av,     cudaFuncAttributeMaxDynamicSharedMemorySize, SMEM_BYTES);

    // 1) convert x; transpose+convert all W's (one launch)
    {
        int n4 = MTOT * DIM / 4;
        conv_x<<<n4 / 256, 256>>>((const float4*)x, (__half2*)x16, n4);
        dim3 tb(32, 8), tg(32, 32, 3);
        tconv_w<<<tg, tb>>>(Wq, Wk, Wv, wt16);
    }

    dim3 blk(256);

    // 2) Q/K/V projections in one launch (z = 0,1,2)
    {
        dim3 g(DKV / TILE, MTOT / TILE, 3);
        gemm_proj<<<g, blk, SMEM_BYTES>>>(x16, wt16, bq, bk, bv, q16, k16, vt16);
    }

    // 3) E = exp(Q K^T / 32 + mask) fp16, per-tile row sums   (per batch)
    {
        dim3 g(SEQ / TILE, SEQ / TILE, BATCH);
        gemm_scores<<<g, blk, SMEM_BYTES>>>(q16, k16, mask, Ep, rsp);
    }

    // 4) inv[row] = 1 / rowsum
    inv_rows<<<MTOT / 256, 256>>>(rsp, ivp);

    // 5) out = inv * (E @ V)
    {
        dim3 g(DKV / TILE, SEQ / TILE, BATCH);
        gemm_av<<<g, blk, SMEM_BYTES>>>(Ep, vt16, ivp, out);
    }
}

// round 11
// speedup vs baseline: 1.0799x; 1.0266x over previous
#include <cuda_runtime.h>
#include <cuda_fp16.h>
#include <cstdint>
#include <math.h>

// ---------------------------------------------------------------------------
// Fixed problem: B=4, S=2048, D=DK=1024. M = B*S = 8192.
// R11: fp16 HMMA 128x128 (8 warps 2x4, 2 CTA/SM) with an in-chunk software
// pipeline: ldsm of the next (kk,mi) fragment overlaps the 4 MMAs of the
// current one (minimal double buffers: A 2x4 regs, B 2x8 regs). Pure __expf.
// Softmax normalization folded into AV epilogue; E stored fp16 unnormalized.
// ---------------------------------------------------------------------------
#define BATCH 4
#define SEQ   2048
#define DIM   1024
#define DKV   1024
#define MTOT  (BATCH * SEQ)

#define TILE  128
#define KC    64          // fp16 elements per K-chunk (128B rows, SW128)

// ---------------- scratch (device globals; no allocation) -------------------
__device__ __half g_x16[(size_t)MTOT * DIM];
__device__ __half g_wt16[3][(size_t)DIM * DKV];          // W^T (contiguous)
__device__ __half g_q16[(size_t)MTOT * DKV];
__device__ __half g_k16[(size_t)MTOT * DKV];
__device__ __half g_vt16[(size_t)MTOT * DKV];            // [B][DKV][SEQ]
__device__ __half g_E [(size_t)BATCH * SEQ * SEQ];       // exp(scores), fp16
__device__ float  g_rsum[(size_t)MTOT * 16];
__device__ float  g_inv [(size_t)MTOT];

// ---------------- PTX helpers ----------------------------------------------
static __device__ __forceinline__ uint32_t smem_u32(const void* p) {
    uint32_t a;
    asm("{ .reg .u64 t; cvta.to.shared.u64 t, %1; cvt.u32.u64 %0, t; }" : "=r"(a) : "l"(p));
    return a;
}
static __device__ __forceinline__ void cp16(uint32_t dst, const void* src) {
    asm volatile("cp.async.cg.shared.global [%0], [%1], 16;" :: "r"(dst), "l"(src) : "memory");
}
static __device__ __forceinline__ void cp_commit() {
    asm volatile("cp.async.commit_group;" ::: "memory");
}
static __device__ __forceinline__ void ldsm4(uint32_t* r, uint32_t addr) {
    asm volatile("ldmatrix.sync.aligned.m8n8.x4.shared.b16 {%0,%1,%2,%3}, [%4];"
                 : "=r"(r[0]), "=r"(r[1]), "=r"(r[2]), "=r"(r[3]) : "r"(addr));
}
static __device__ __forceinline__ void mma16816(float* c, const uint32_t* a, const uint32_t* b) {
    asm volatile(
        "mma.sync.aligned.m16n8k16.row.col.f32.f16.f16.f32 "
        "{%0,%1,%2,%3}, {%4,%5,%6,%7}, {%8,%9}, {%0,%1,%2,%3};"
        : "+f"(c[0]), "+f"(c[1]), "+f"(c[2]), "+f"(c[3])
        : "r"(a[0]), "r"(a[1]), "r"(a[2]), "r"(a[3]), "r"(b[0]), "r"(b[1]));
}
static __device__ __forceinline__ uint32_t sw128(uint32_t off) {
    return off ^ ((off >> 3) & 0x70);
}

// Stage (32KB): A @0 (16KB), B @16KB. 128 rows x 128B, SW128 swizzle.
#define STAGE_BYTES 32768
#define NSTAGE      3
#define SMEM_BYTES  (1024 + NSTAGE * STAGE_BYTES)

static __device__ __forceinline__ void load_chunk(
    const __half* A, const __half* B, int K,
    int m0, int n0, int koff, uint32_t stage, int tid)
{
    #pragma unroll
    for (int j = 0; j < 4; j++) {
        int id = tid + j * 256;                 // 0..1023
        int r  = id >> 3;                       // 0..127
        int cb = (id & 7) << 4;                 // byte col in 128B row
        uint32_t sw = sw128((uint32_t)((r << 7) + cb));
        cp16(stage +         sw, A + (long)(m0 + r) * K + koff + (cb >> 1));
        cp16(stage + 16384 + sw, B + (long)(n0 + r) * K + koff + (cb >> 1));
    }
    cp_commit();
}

// Shared prolog + pipelined mainloop + accumulator->tile spill.
// In-chunk pipeline: fragment for step (kk,mi+1) loads while (kk,mi) MMAs run.
#define GEMM_BODY(Aptr, Bptr, Kdim)                                              \
    extern __shared__ char smraw[];                                              \
    const int tid = threadIdx.x;                                                 \
    const int wid = tid >> 5;                                                    \
    const int lid = tid & 31;                                                    \
    const int z   = blockIdx.z;                                                  \
    const int m0  = blockIdx.y * TILE;                                           \
    const int n0  = blockIdx.x * TILE;                                           \
    const uint32_t smb = (smem_u32(smraw) + 1023u) & ~1023u;                     \
    uint32_t stg[NSTAGE];                                                        \
    _Pragma("unroll")                                                            \
    for (int s = 0; s < NSTAGE; s++) stg[s] = smb + s * STAGE_BYTES;             \
    const int wm = (wid >> 2) * 64;                                              \
    const int wn = (wid & 3) * 32;                                               \
    const int aRow  = wm + (lid & 15);                                           \
    const int aColB = (lid >> 4) << 4;                                           \
    const int bRow  = wn + (((lid >> 4) & 1) << 3) + (lid & 7);                  \
    const int bColB = ((lid >> 3) & 1) << 4;                                     \
    uint32_t aOff[4], bOff[2];                                                   \
    _Pragma("unroll")                                                            \
    for (int t = 0; t < 4; t++)                                                  \
        aOff[t] = sw128((uint32_t)((aRow + t * 16) << 7) + aColB);               \
    _Pragma("unroll")                                                            \
    for (int t = 0; t < 2; t++)                                                  \
        bOff[t] = sw128((uint32_t)((bRow + t * 16) << 7) + bColB) + 16384;       \
    float acc[4][4][4];                                                          \
    _Pragma("unroll")                                                            \
    for (int mi = 0; mi < 4; mi++)                                               \
        _Pragma("unroll")                                                        \
        for (int ni = 0; ni < 4; ni++)                                           \
            _Pragma("unroll")                                                    \
            for (int r = 0; r < 4; r++) acc[mi][ni][r] = 0.0f;                   \
    uint32_t fa[2][4], fb[2][8];                                                 \
    const int NC = (Kdim) / KC;                                                  \
    load_chunk((Aptr), (Bptr), (Kdim), m0, n0, 0, stg[0], tid);                  \
    load_chunk((Aptr), (Bptr), (Kdim), m0, n0, KC, stg[1], tid);                 \
    uint32_t cur = stg[0];                                                       \
    int nxt = 2;                                                                 \
    for (int i = 0; i < NC; i++) {                                               \
        asm volatile("cp.async.wait_group 1;" ::: "memory");                     \
        __syncthreads();                                                         \
        if (i + 2 < NC)                                                          \
            load_chunk((Aptr), (Bptr), (Kdim), m0, n0, (i + 2) * KC, stg[nxt], tid); \
        else                                                                     \
            cp_commit();                                                         \
        /* chunk prologue: first B pair + first A fragment */                    \
        ldsm4(&fb[0][0], cur + bOff[0]);                                         \
        ldsm4(&fb[0][4], cur + bOff[1]);                                         \
        ldsm4(fa[0],     cur + aOff[0]);                                         \
        _Pragma("unroll")                                                        \
        for (int kk = 0; kk < 4; kk++) {                                         \
            const uint32_t xc = (uint32_t)(kk << 5);                             \
            const uint32_t xn = (uint32_t)((kk + 1) << 5);                       \
            _Pragma("unroll")                                                    \
            for (int mi = 0; mi < 4; mi++) {                                     \
                const int p  = (kk * 4 + mi) & 1;                                \
                const int np = p ^ 1;                                            \
                if (mi < 3) {                                                    \
                    ldsm4(fa[np], cur + (aOff[mi + 1] ^ xc));                     \
                } else if (kk < 3) {                                             \
                    ldsm4(&fb[(kk + 1) & 1][0], cur + (bOff[0] ^ xn));           \
                    ldsm4(&fb[(kk + 1) & 1][4], cur + (bOff[1] ^ xn));           \
                    ldsm4(fa[np], cur + (aOff[0] ^ xn));                         \
                }                                                                \
                uint32_t* B = fb[kk & 1];                                        \
                mma16816(acc[mi][0], fa[p], B + 0);                              \
                mma16816(acc[mi][1], fa[p], B + 2);                              \
                mma16816(acc[mi][2], fa[p], B + 4);                              \
                mma16816(acc[mi][3], fa[p], B + 6);                              \
            }                                                                    \
        }                                                                        \
        cur = stg[(i + 1) % NSTAGE];                                             \
        nxt = (nxt + 1) % NSTAGE;                                                \
    }                                                                            \
    __syncthreads();                                                             \
    float* tile = (float*)(smraw + (smb - smem_u32(smraw)));                     \
    {                                                                            \
        const int r0 = lid >> 2;                                                 \
        const int c0 = (lid & 3) * 2;                                            \
        _Pragma("unroll")                                                        \
        for (int mi = 0; mi < 4; mi++)                                           \
            _Pragma("unroll")                                                    \
            for (int ni = 0; ni < 4; ni++) {                                     \
                int m = wm + mi * 16 + r0;                                       \
                int n = wn + ni * 8 + c0;                                        \
                tile[m * 129 + n]           = acc[mi][ni][0];                    \
                tile[m * 129 + n + 1]       = acc[mi][ni][1];                    \
                tile[(m + 8) * 129 + n]     = acc[mi][ni][2];                    \
                tile[(m + 8) * 129 + n + 1] = acc[mi][ni][3];                    \
            }                                                                    \
    }                                                                            \
    __syncthreads();

// ---------------- merged projection GEMM: z = 0(Q), 1(K), 2(V) --------------
__global__ void __launch_bounds__(256, 2)
gemm_proj(const __half* __restrict__ A, const __half* __restrict__ Wt,
          const float* __restrict__ b0, const float* __restrict__ b1,
          const float* __restrict__ b2,
          __half* __restrict__ o0, __half* __restrict__ o1,
          __half* __restrict__ o2)
{
    GEMM_BODY(A, Wt + (long)blockIdx.z * DIM * DKV, DIM)

    const float* bias = (z == 0) ? b0 : (z == 1) ? b1 : b2;
    if (z < 2) {
        __half* dst = (z == 0) ? o0 : o1;
        for (int idx = tid; idx < TILE * TILE; idx += 256) {
            int r = idx >> 7, c = idx & 127;
            float v = tile[r * 129 + c] + bias[n0 + c];
            dst[(long)(m0 + r) * DKV + n0 + c] = __float2half(v);
        }
    } else {
        // V: write transposed Vt[b][n][seq]
        const int b = m0 >> 11, seq0 = m0 & 2047;
        for (int idx = tid; idx < TILE * TILE; idx += 256) {
            int n = idx >> 7, mm = idx & 127;
            float v = tile[mm * 129 + n] + bias[n0 + n];
            o2[(long)b * DKV * SEQ + (long)(n0 + n) * SEQ + seq0 + mm] = __float2half(v);
        }
    }
}

// ---------------- scores GEMM: E = exp(QK^T/32 + mask) fp16 + rowsums -------
__global__ void __launch_bounds__(256, 2)
gemm_scores(const __half* __restrict__ Q, const __half* __restrict__ Km,
            const float* __restrict__ mask, __half* __restrict__ Eh,
            float* __restrict__ rsum)
{
    GEMM_BODY(Q + (long)blockIdx.z * SEQ * DKV,
              Km + (long)blockIdx.z * SEQ * DKV, DKV)

    const long bo = (long)z * SEQ * SEQ;
    for (int idx = tid; idx < TILE * TILE; idx += 256) {
        int r = idx >> 7, c = idx & 127;
        long o = bo + (long)(m0 + r) * SEQ + n0 + c;
        float e = __expf(__fmaf_rn(tile[r * 129 + c], 0.03125f, mask[o]));
        __half eh = __float2half(e);
        Eh[o] = eh;
        // rowsum over the fp16-rounded values so numerator/denominator
        // quantization cancels in the final softmax ratio
        tile[r * 129 + c] = __half2float(eh);
    }
    __syncthreads();
    if (tid < 128) {
        float s = 0.0f;
        #pragma unroll 8
        for (int c = 0; c < 128; c++) s += tile[tid * 129 + c];
        rsum[((long)(z << 11) + m0 + tid) * 16 + blockIdx.x] = s;
    }
}

// ---------------- AV GEMM: out = inv[row] * (E @ V) -------------------------
__global__ void __launch_bounds__(256, 2)
gemm_av(const __half* __restrict__ E, const __half* __restrict__ Vt,
        const float* __restrict__ inv, float* __restrict__ outF)
{
    GEMM_BODY(E + (long)blockIdx.z * SEQ * SEQ,
              Vt + (long)blockIdx.z * DKV * SEQ, SEQ)

    const long bo = (long)z * SEQ * DKV;
    for (int idx = tid; idx < TILE * TILE; idx += 256) {
        int r = idx >> 7, c = idx & 127;
        float iv = inv[(z << 11) + m0 + r];
        outF[bo + (long)(m0 + r) * DKV + n0 + c] = tile[r * 129 + c] * iv;
    }
}

// ---------------- 1/rowsum reduce -------------------------------------------
__global__ void __launch_bounds__(256)
inv_rows(const float* __restrict__ rsum, float* __restrict__ inv)
{
    int R = blockIdx.x * 256 + threadIdx.x;
    float s = 0.0f;
    #pragma unroll
    for (int t = 0; t < 16; t++) s += rsum[(long)R * 16 + t];
    inv[R] = 1.0f / s;
}

// ---------------- x -> fp16 --------------------------------------------------
__global__ void __launch_bounds__(256)
conv_x(const float4* __restrict__ in, __half2* __restrict__ out, int n4)
{
    int i = blockIdx.x * 256 + threadIdx.x;
    if (i >= n4) return;
    float4 v = in[i];
    out[i * 2]     = __floats2half2_rn(v.x, v.y);
    out[i * 2 + 1] = __floats2half2_rn(v.z, v.w);
}

// ---------------- transpose + convert W (z = 0,1,2 merged) ------------------
__global__ void __launch_bounds__(256)
tconv_w(const float* __restrict__ W0, const float* __restrict__ W1,
        const float* __restrict__ W2, __half* __restrict__ out)
{
    __shared__ float t[32][33];
    const int zz = blockIdx.z;
    const float* in = (zz == 0) ? W0 : (zz == 1) ? W1 : W2;
    __half* o = out + (long)zz * DIM * DKV;
    const int bx = blockIdx.x * 32, by = blockIdx.y * 32;
    const int tx = threadIdx.x, ty = threadIdx.y;       // block (32,8)
    #pragma unroll
    for (int k = 0; k < 32; k += 8)
        t[ty + k][tx] = in[(long)(by + ty + k) * DKV + bx + tx];
    __syncthreads();
    #pragma unroll
    for (int k = 0; k < 32; k += 8)
        o[(long)(bx + ty + k) * DIM + by + tx] = __float2half(t[tx][ty + k]);
}

// ---------------------------------------------------------------------------
extern "C" void kernel_launch(void* const* d_in, const int* in_sizes, int n_in,
                              void* d_out, int out_size)
{
    const float* x    = (const float*)d_in[0];
    const float* mask = (const float*)d_in[1];
    const float* Wq   = (const float*)d_in[2];
    const float* bq   = (const float*)d_in[3];
    const float* Wk   = (const float*)d_in[4];
    const float* bk   = (const float*)d_in[5];
    const float* Wv   = (const float*)d_in[6];
    const float* bv   = (const float*)d_in[7];
    float* out = (float*)d_out;

    __half *x16, *wt16, *q16, *k16, *vt16, *Ep;
    float *rsp, *ivp;
    cudaGetSymbolAddress((void**)&x16,  g_x16);
    cudaGetSymbolAddress((void**)&wt16, g_wt16);
    cudaGetSymbolAddress((void**)&q16,  g_q16);
    cudaGetSymbolAddress((void**)&k16,  g_k16);
    cudaGetSymbolAddress((void**)&vt16, g_vt16);
    cudaGetSymbolAddress((void**)&Ep,   g_E);
    cudaGetSymbolAddress((void**)&rsp,  g_rsum);
    cudaGetSymbolAddress((void**)&ivp,  g_inv);

    cudaFuncSetAttribute(gemm_proj,   cudaFuncAttributeMaxDynamicSharedMemorySize, SMEM_BYTES);
    cudaFuncSetAttribute(gemm_scores, cudaFuncAttributeMaxDynamicSharedMemorySize, SMEM_BYTES);
    cudaFuncSetAttribute(gemm_av,     cudaFuncAttributeMaxDynamicSharedMemorySize, SMEM_BYTES);

    // 1) convert x; transpose+convert all W's (one launch)
    {
        int n4 = MTOT * DIM / 4;
        conv_x<<<n4 / 256, 256>>>((const float4*)x, (__half2*)x16, n4);
        dim3 tb(32, 8), tg(32, 32, 3);
        tconv_w<<<tg, tb>>>(Wq, Wk, Wv, wt16);
    }

    dim3 blk(256);

    // 2) Q/K/V projections in one launch (z = 0,1,2)
    {
        dim3 g(DKV / TILE, MTOT / TILE, 3);
        gemm_proj<<<g, blk, SMEM_BYTES>>>(x16, wt16, bq, bk, bv, q16, k16, vt16);
    }

    // 3) E = exp(Q K^T / 32 + mask) fp16, per-tile row sums   (per batch)
    {
        dim3 g(SEQ / TILE, SEQ / TILE, BATCH);
        gemm_scores<<<g, blk, SMEM_BYTES>>>(q16, k16, mask, Ep, rsp);
    }

    // 4) inv[row] = 1 / rowsum
    inv_rows<<<MTOT / 256, 256>>>(rsp, ivp);

    // 5) out = inv * (E @ V)
    {
        dim3 g(DKV / TILE, SEQ / TILE, BATCH);
        gemm_av<<<g, blk, SMEM_BYTES>>>(Ep, vt16, ivp, out);
    }
}

// round 12
// speedup vs baseline: 1.1098x; 1.0278x over previous
#include <cuda_runtime.h>
#include <cuda_fp16.h>
#include <cstdint>
#include <math.h>

// ---------------------------------------------------------------------------
// Fixed problem: B=4, S=2048, D=DK=1024. M = B*S = 8192.
// R12: algebraic FLOP cut. QK^T = x (Wq Wk^T) x^T + u 1^T + 1 t^T + c.
//   M = Wq Wk^T precomputed (tiny GEMM); G = x M (one proj instead of Q,K);
//   scores = G x^T with rank-1 bias terms folded into the exp epilogue.
// GEMM engine = R11 (fp16 HMMA, in-chunk sw pipeline, 8 warps, 2 CTA/SM).
// ---------------------------------------------------------------------------
#define BATCH 4
#define SEQ   2048
#define DIM   1024
#define DKV   1024
#define MTOT  (BATCH * SEQ)

#define TILE  128
#define KC    64          // fp16 elements per K-chunk (128B rows, SW128)

// ---------------- scratch (device globals; no allocation) -------------------
__device__ __half g_x16[(size_t)MTOT * DIM];
__device__ __half g_wq16[(size_t)DIM * DKV];             // Wq fp16 (plain)
__device__ __half g_wk16[(size_t)DIM * DKV];             // Wk fp16 (plain)
__device__ __half g_wvt16[(size_t)DKV * DIM];            // Wv^T fp16
__device__ __half g_mt16[(size_t)DIM * DIM];             // (Wq Wk^T)^T fp16
__device__ __half g_g16[(size_t)MTOT * DIM];             // G = x M
__device__ __half g_vt16[(size_t)MTOT * DKV];            // V^T per batch
__device__ __half g_E [(size_t)BATCH * SEQ * SEQ];       // exp(scores), fp16
__device__ float  g_rsum[(size_t)MTOT * 16];
__device__ float  g_inv [(size_t)MTOT];
__device__ float  g_wu[DIM];                             // Wq bk
__device__ float  g_wt[DIM];                             // Wk bq
__device__ float  g_u [(size_t)MTOT];                    // x (Wq bk)
__device__ float  g_t [(size_t)MTOT];                    // x (Wk bq)
__device__ float  g_c [1];                               // bq . bk

// ---------------- PTX helpers ----------------------------------------------
static __device__ __forceinline__ uint32_t smem_u32(const void* p) {
    uint32_t a;
    asm("{ .reg .u64 t; cvta.to.shared.u64 t, %1; cvt.u32.u64 %0, t; }" : "=r"(a) : "l"(p));
    return a;
}
static __device__ __forceinline__ void cp16(uint32_t dst, const void* src) {
    asm volatile("cp.async.cg.shared.global [%0], [%1], 16;" :: "r"(dst), "l"(src) : "memory");
}
static __device__ __forceinline__ void cp_commit() {
    asm volatile("cp.async.commit_group;" ::: "memory");
}
static __device__ __forceinline__ void ldsm4(uint32_t* r, uint32_t addr) {
    asm volatile("ldmatrix.sync.aligned.m8n8.x4.shared.b16 {%0,%1,%2,%3}, [%4];"
                 : "=r"(r[0]), "=r"(r[1]), "=r"(r[2]), "=r"(r[3]) : "r"(addr));
}
static __device__ __forceinline__ void mma16816(float* c, const uint32_t* a, const uint32_t* b) {
    asm volatile(
        "mma.sync.aligned.m16n8k16.row.col.f32.f16.f16.f32 "
        "{%0,%1,%2,%3}, {%4,%5,%6,%7}, {%8,%9}, {%0,%1,%2,%3};"
        : "+f"(c[0]), "+f"(c[1]), "+f"(c[2]), "+f"(c[3])
        : "r"(a[0]), "r"(a[1]), "r"(a[2]), "r"(a[3]), "r"(b[0]), "r"(b[1]));
}
static __device__ __forceinline__ uint32_t sw128(uint32_t off) {
    return off ^ ((off >> 3) & 0x70);
}

// Stage (32KB): A @0 (16KB), B @16KB. 128 rows x 128B, SW128 swizzle.
#define STAGE_BYTES 32768
#define NSTAGE      3
#define SMEM_BYTES  (1024 + NSTAGE * STAGE_BYTES)

static __device__ __forceinline__ void load_chunk(
    const __half* A, const __half* B, int K,
    int m0, int n0, int koff, uint32_t stage, int tid)
{
    #pragma unroll
    for (int j = 0; j < 4; j++) {
        int id = tid + j * 256;                 // 0..1023
        int r  = id >> 3;                       // 0..127
        int cb = (id & 7) << 4;                 // byte col in 128B row
        uint32_t sw = sw128((uint32_t)((r << 7) + cb));
        cp16(stage +         sw, A + (long)(m0 + r) * K + koff + (cb >> 1));
        cp16(stage + 16384 + sw, B + (long)(n0 + r) * K + koff + (cb >> 1));
    }
    cp_commit();
}

// Shared prolog + pipelined mainloop + accumulator->tile spill (R11 engine).
#define GEMM_BODY(Aptr, Bptr, Kdim)                                              \
    extern __shared__ char smraw[];                                              \
    const int tid = threadIdx.x;                                                 \
    const int wid = tid >> 5;                                                    \
    const int lid = tid & 31;                                                    \
    const int z   = blockIdx.z;                                                  \
    const int m0  = blockIdx.y * TILE;                                           \
    const int n0  = blockIdx.x * TILE;                                           \
    const uint32_t smb = (smem_u32(smraw) + 1023u) & ~1023u;                     \
    uint32_t stg[NSTAGE];                                                        \
    _Pragma("unroll")                                                            \
    for (int s = 0; s < NSTAGE; s++) stg[s] = smb + s * STAGE_BYTES;             \
    const int wm = (wid >> 2) * 64;                                              \
    const int wn = (wid & 3) * 32;                                               \
    const int aRow  = wm + (lid & 15);                                           \
    const int aColB = (lid >> 4) << 4;                                           \
    const int bRow  = wn + (((lid >> 4) & 1) << 3) + (lid & 7);                  \
    const int bColB = ((lid >> 3) & 1) << 4;                                     \
    uint32_t aOff[4], bOff[2];                                                   \
    _Pragma("unroll")                                                            \
    for (int t = 0; t < 4; t++)                                                  \
        aOff[t] = sw128((uint32_t)((aRow + t * 16) << 7) + aColB);               \
    _Pragma("unroll")                                                            \
    for (int t = 0; t < 2; t++)                                                  \
        bOff[t] = sw128((uint32_t)((bRow + t * 16) << 7) + bColB) + 16384;       \
    float acc[4][4][4];                                                          \
    _Pragma("unroll")                                                            \
    for (int mi = 0; mi < 4; mi++)                                               \
        _Pragma("unroll")                                                        \
        for (int ni = 0; ni < 4; ni++)                                           \
            _Pragma("unroll")                                                    \
            for (int r = 0; r < 4; r++) acc[mi][ni][r] = 0.0f;                   \
    uint32_t fa[2][4], fb[2][8];                                                 \
    const int NC = (Kdim) / KC;                                                  \
    load_chunk((Aptr), (Bptr), (Kdim), m0, n0, 0, stg[0], tid);                  \
    load_chunk((Aptr), (Bptr), (Kdim), m0, n0, KC, stg[1], tid);                 \
    uint32_t cur = stg[0];                                                       \
    int nxt = 2;                                                                 \
    for (int i = 0; i < NC; i++) {                                               \
        asm volatile("cp.async.wait_group 1;" ::: "memory");                     \
        __syncthreads();                                                         \
        if (i + 2 < NC)                                                          \
            load_chunk((Aptr), (Bptr), (Kdim), m0, n0, (i + 2) * KC, stg[nxt], tid); \
        else                                                                     \
            cp_commit();                                                         \
        ldsm4(&fb[0][0], cur + bOff[0]);                                         \
        ldsm4(&fb[0][4], cur + bOff[1]);                                         \
        ldsm4(fa[0],     cur + aOff[0]);                                         \
        _Pragma("unroll")                                                        \
        for (int kk = 0; kk < 4; kk++) {                                         \
            const uint32_t xc = (uint32_t)(kk << 5);                             \
            const uint32_t xn = (uint32_t)((kk + 1) << 5);                       \
            _Pragma("unroll")                                                    \
            for (int mi = 0; mi < 4; mi++) {                                     \
                const int p  = (kk * 4 + mi) & 1;                                \
                const int np = p ^ 1;                                            \
                if (mi < 3) {                                                    \
                    ldsm4(fa[np], cur + (aOff[mi + 1] ^ xc));                     \
                } else if (kk < 3) {                                             \
                    ldsm4(&fb[(kk + 1) & 1][0], cur + (bOff[0] ^ xn));           \
                    ldsm4(&fb[(kk + 1) & 1][4], cur + (bOff[1] ^ xn));           \
                    ldsm4(fa[np], cur + (aOff[0] ^ xn));                         \
                }                                                                \
                uint32_t* B = fb[kk & 1];                                        \
                mma16816(acc[mi][0], fa[p], B + 0);                              \
                mma16816(acc[mi][1], fa[p], B + 2);                              \
                mma16816(acc[mi][2], fa[p], B + 4);                              \
                mma16816(acc[mi][3], fa[p], B + 6);                              \
            }                                                                    \
        }                                                                        \
        cur = stg[(i + 1) % NSTAGE];                                             \
        nxt = (nxt + 1) % NSTAGE;                                                \
    }                                                                            \
    __syncthreads();                                                             \
    float* tile = (float*)(smraw + (smb - smem_u32(smraw)));                     \
    {                                                                            \
        const int r0 = lid >> 2;                                                 \
        const int c0 = (lid & 3) * 2;                                            \
        _Pragma("unroll")                                                        \
        for (int mi = 0; mi < 4; mi++)                                           \
            _Pragma("unroll")                                                    \
            for (int ni = 0; ni < 4; ni++) {                                     \
                int m = wm + mi * 16 + r0;                                       \
                int n = wn + ni * 8 + c0;                                        \
                tile[m * 129 + n]           = acc[mi][ni][0];                    \
                tile[m * 129 + n + 1]       = acc[mi][ni][1];                    \
                tile[(m + 8) * 129 + n]     = acc[mi][ni][2];                    \
                tile[(m + 8) * 129 + n + 1] = acc[mi][ni][3];                    \
            }                                                                    \
    }                                                                            \
    __syncthreads();

// ---------------- M = Wq Wk^T, written transposed fp16 ----------------------
__global__ void __launch_bounds__(256, 2)
gemm_wm(const __half* __restrict__ Wq, const __half* __restrict__ Wk,
        __half* __restrict__ Mt)
{
    GEMM_BODY(Wq, Wk, DIM)
    (void)z;
    for (int idx = tid; idx < TILE * TILE; idx += 256) {
        int n = idx >> 7, mm = idx & 127;
        Mt[(long)(n0 + n) * DIM + m0 + mm] = __float2half(tile[mm * 129 + n]);
    }
}

// ---------------- proj: z=0: G = x M (plain); z=1: Vt = (x Wv + bv)^T -------
__global__ void __launch_bounds__(256, 2)
gemm_proj(const __half* __restrict__ A, const __half* __restrict__ Bmt,
          const __half* __restrict__ Bwv, const float* __restrict__ bv,
          __half* __restrict__ oG, __half* __restrict__ oVt)
{
    GEMM_BODY(A, (blockIdx.z == 0 ? Bmt : Bwv), DIM)

    if (z == 0) {
        for (int idx = tid; idx < TILE * TILE; idx += 256) {
            int r = idx >> 7, c = idx & 127;
            oG[(long)(m0 + r) * DKV + n0 + c] = __float2half(tile[r * 129 + c]);
        }
    } else {
        const int b = m0 >> 11, seq0 = m0 & 2047;
        for (int idx = tid; idx < TILE * TILE; idx += 256) {
            int n = idx >> 7, mm = idx & 127;
            float v = tile[mm * 129 + n] + bv[n0 + n];
            oVt[(long)b * DKV * SEQ + (long)(n0 + n) * SEQ + seq0 + mm] = __float2half(v);
        }
    }
}

// ---------------- scores: E = exp((G x^T + u + t + c)/32 + mask) fp16 -------
__global__ void __launch_bounds__(256, 2)
gemm_scores(const __half* __restrict__ G, const __half* __restrict__ X,
            const float* __restrict__ mask, const float* __restrict__ u,
            const float* __restrict__ tv, const float* __restrict__ cp,
            __half* __restrict__ Eh, float* __restrict__ rsum)
{
    GEMM_BODY(G + (long)blockIdx.z * SEQ * DKV,
              X + (long)blockIdx.z * SEQ * DIM, DIM)

    const long bo = (long)z * SEQ * SEQ;
    const float cv = cp[0];
    for (int idx = tid; idx < TILE * TILE; idx += 256) {
        int r = idx >> 7, c = idx & 127;
        long o = bo + (long)(m0 + r) * SEQ + n0 + c;
        float s = tile[r * 129 + c] + u[(z << 11) + m0 + r] + tv[(z << 11) + n0 + c] + cv;
        float e = __expf(__fmaf_rn(s, 0.03125f, mask[o]));
        __half eh = __float2half(e);
        Eh[o] = eh;
        tile[r * 129 + c] = __half2float(eh);
    }
    __syncthreads();
    if (tid < 128) {
        float s = 0.0f;
        #pragma unroll 8
        for (int c = 0; c < 128; c++) s += tile[tid * 129 + c];
        rsum[((long)(z << 11) + m0 + tid) * 16 + blockIdx.x] = s;
    }
}

// ---------------- AV GEMM: out = inv[row] * (E @ V) -------------------------
__global__ void __launch_bounds__(256, 2)
gemm_av(const __half* __restrict__ E, const __half* __restrict__ Vt,
        const float* __restrict__ inv, float* __restrict__ outF)
{
    GEMM_BODY(E + (long)blockIdx.z * SEQ * SEQ,
              Vt + (long)blockIdx.z * DKV * SEQ, SEQ)

    const long bo = (long)z * SEQ * DKV;
    for (int idx = tid; idx < TILE * TILE; idx += 256) {
        int r = idx >> 7, c = idx & 127;
        float iv = inv[(z << 11) + m0 + r];
        outF[bo + (long)(m0 + r) * DKV + n0 + c] = tile[r * 129 + c] * iv;
    }
}

// ---------------- 1/rowsum reduce -------------------------------------------
__global__ void __launch_bounds__(256)
inv_rows(const float* __restrict__ rsum, float* __restrict__ inv)
{
    int R = blockIdx.x * 256 + threadIdx.x;
    float s = 0.0f;
    #pragma unroll
    for (int t = 0; t < 16; t++) s += rsum[(long)R * 16 + t];
    inv[R] = 1.0f / s;
}

// ---------------- x -> fp16 --------------------------------------------------
__global__ void __launch_bounds__(256)
conv_x(const float4* __restrict__ in, __half2* __restrict__ out, int n4)
{
    int i = blockIdx.x * 256 + threadIdx.x;
    if (i >= n4) return;
    float4 v = in[i];
    out[i * 2]     = __floats2half2_rn(v.x, v.y);
    out[i * 2 + 1] = __floats2half2_rn(v.z, v.w);
}

// ---------------- plain fp16 convert of Wq (z=0) / Wk (z=1) -----------------
__global__ void __launch_bounds__(256)
conv_w(const float4* __restrict__ Wq, const float4* __restrict__ Wk,
       __half2* __restrict__ oq, __half2* __restrict__ ok, int n4)
{
    int i = blockIdx.x * 256 + threadIdx.x;
    if (i >= n4) return;
    const float4* in = blockIdx.y ? Wk : Wq;
    __half2* out = blockIdx.y ? ok : oq;
    float4 v = in[i];
    out[i * 2]     = __floats2half2_rn(v.x, v.y);
    out[i * 2 + 1] = __floats2half2_rn(v.z, v.w);
}

// ---------------- transpose + convert Wv ------------------------------------
__global__ void __launch_bounds__(256)
tconv_wv(const float* __restrict__ in, __half* __restrict__ out)
{
    __shared__ float t[32][33];
    const int bx = blockIdx.x * 32, by = blockIdx.y * 32;
    const int tx = threadIdx.x, ty = threadIdx.y;       // block (32,8)
    #pragma unroll
    for (int k = 0; k < 32; k += 8)
        t[ty + k][tx] = in[(long)(by + ty + k) * DKV + bx + tx];
    __syncthreads();
    #pragma unroll
    for (int k = 0; k < 32; k += 8)
        out[(long)(bx + ty + k) * DIM + by + tx] = __float2half(t[tx][ty + k]);
}

// ---------------- wu = Wq bk, wt = Wk bq, c = bq.bk -------------------------
__global__ void __launch_bounds__(256)
vecprep(const float* __restrict__ Wq, const float* __restrict__ Wk,
        const float* __restrict__ bq, const float* __restrict__ bk,
        float* __restrict__ wu, float* __restrict__ wt, float* __restrict__ cp)
{
    int d = blockIdx.x * 8 + (threadIdx.x >> 5);
    int l = threadIdx.x & 31;
    float su = 0.0f, st = 0.0f;
    for (int k = l; k < DIM; k += 32) {
        su += Wq[(long)d * DKV + k] * bk[k];
        st += Wk[(long)d * DKV + k] * bq[k];
    }
    #pragma unroll
    for (int s = 16; s > 0; s >>= 1) {
        su += __shfl_down_sync(0xffffffff, su, s);
        st += __shfl_down_sync(0xffffffff, st, s);
    }
    if (l == 0) { wu[d] = su; wt[d] = st; }
    if (blockIdx.x == 0 && threadIdx.x < 32) {
        float sc = 0.0f;
        for (int k = l; k < DIM; k += 32) sc += bq[k] * bk[k];
        #pragma unroll
        for (int s = 16; s > 0; s >>= 1) sc += __shfl_down_sync(0xffffffff, sc, s);
        if (l == 0) cp[0] = sc;
    }
}

// ---------------- u = x wu, t = x wt (one warp per row) ---------------------
__global__ void __launch_bounds__(256)
ut_gemv(const __half* __restrict__ x16, const float* __restrict__ wu,
        const float* __restrict__ wt, float* __restrict__ u, float* __restrict__ t)
{
    int q = blockIdx.x * 8 + (threadIdx.x >> 5);
    int l = threadIdx.x & 31;
    const __half2* xr = (const __half2*)(x16 + (long)q * DIM);
    const float2* wu2 = (const float2*)wu;
    const float2* wt2 = (const float2*)wt;
    float su = 0.0f, st = 0.0f;
    for (int i = l; i < DIM / 2; i += 32) {
        float2 xf = __half22float2(xr[i]);
        float2 a = wu2[i], b = wt2[i];
        su += xf.x * a.x + xf.y * a.y;
        st += xf.x * b.x + xf.y * b.y;
    }
    #pragma unroll
    for (int s = 16; s > 0; s >>= 1) {
        su += __shfl_down_sync(0xffffffff, su, s);
        st += __shfl_down_sync(0xffffffff, st, s);
    }
    if (l == 0) { u[q] = su; t[q] = st; }
}

// ---------------------------------------------------------------------------
extern "C" void kernel_launch(void* const* d_in, const int* in_sizes, int n_in,
                              void* d_out, int out_size)
{
    const float* x    = (const float*)d_in[0];
    const float* mask = (const float*)d_in[1];
    const float* Wq   = (const float*)d_in[2];
    const float* bq   = (const float*)d_in[3];
    const float* Wk   = (const float*)d_in[4];
    const float* bk   = (const float*)d_in[5];
    const float* Wv   = (const float*)d_in[6];
    const float* bv   = (const float*)d_in[7];
    float* out = (float*)d_out;

    __half *x16, *wq16, *wk16, *wvt16, *mt16, *g16, *vt16, *Ep;
    float *rsp, *ivp, *wup, *wtp, *up, *tp, *cpv;
    cudaGetSymbolAddress((void**)&x16,   g_x16);
    cudaGetSymbolAddress((void**)&wq16,  g_wq16);
    cudaGetSymbolAddress((void**)&wk16,  g_wk16);
    cudaGetSymbolAddress((void**)&wvt16, g_wvt16);
    cudaGetSymbolAddress((void**)&mt16,  g_mt16);
    cudaGetSymbolAddress((void**)&g16,   g_g16);
    cudaGetSymbolAddress((void**)&vt16,  g_vt16);
    cudaGetSymbolAddress((void**)&Ep,    g_E);
    cudaGetSymbolAddress((void**)&rsp,   g_rsum);
    cudaGetSymbolAddress((void**)&ivp,   g_inv);
    cudaGetSymbolAddress((void**)&wup,   g_wu);
    cudaGetSymbolAddress((void**)&wtp,   g_wt);
    cudaGetSymbolAddress((void**)&up,    g_u);
    cudaGetSymbolAddress((void**)&tp,    g_t);
    cudaGetSymbolAddress((void**)&cpv,   g_c);

    cudaFuncSetAttribute(gemm_wm,     cudaFuncAttributeMaxDynamicSharedMemorySize, SMEM_BYTES);
    cudaFuncSetAttribute(gemm_proj,   cudaFuncAttributeMaxDynamicSharedMemorySize, SMEM_BYTES);
    cudaFuncSetAttribute(gemm_scores, cudaFuncAttributeMaxDynamicSharedMemorySize, SMEM_BYTES);
    cudaFuncSetAttribute(gemm_av,     cudaFuncAttributeMaxDynamicSharedMemorySize, SMEM_BYTES);

    // 1) conversions + bias-vector prep
    {
        int n4x = MTOT * DIM / 4;
        conv_x<<<n4x / 256, 256>>>((const float4*)x, (__half2*)x16, n4x);
        int n4w = DIM * DKV / 4;
        dim3 gw(n4w / 256, 2);
        conv_w<<<gw, 256>>>((const float4*)Wq, (const float4*)Wk,
                            (__half2*)wq16, (__half2*)wk16, n4w);
        dim3 tb(32, 8), tg(32, 32);
        tconv_wv<<<tg, tb>>>(Wv, wvt16);
        vecprep<<<DIM / 8, 256>>>(Wq, Wk, bq, bk, wup, wtp, cpv);
        ut_gemv<<<MTOT / 8, 256>>>(x16, wup, wtp, up, tp);
    }

    dim3 blk(256);

    // 2) M = Wq Wk^T (transposed fp16 out)
    {
        dim3 g(DIM / TILE, DIM / TILE, 1);
        gemm_wm<<<g, blk, SMEM_BYTES>>>(wq16, wk16, mt16);
    }

    // 3) z=0: G = x M;  z=1: Vt = (x Wv + bv)^T
    {
        dim3 g(DKV / TILE, MTOT / TILE, 2);
        gemm_proj<<<g, blk, SMEM_BYTES>>>(x16, mt16, wvt16, bv, g16, vt16);
    }

    // 4) E = exp((G x^T + u + t + c)/32 + mask) fp16, per-tile row sums
    {
        dim3 g(SEQ / TILE, SEQ / TILE, BATCH);
        gemm_scores<<<g, blk, SMEM_BYTES>>>(g16, x16, mask, up, tp, cpv, Ep, rsp);
    }

    // 5) inv[row] = 1 / rowsum
    inv_rows<<<MTOT / 256, 256>>>(rsp, ivp);

    // 6) out = inv * (E @ V)
    {
        dim3 g(DKV / TILE, SEQ / TILE, BATCH);
        gemm_av<<<g, blk, SMEM_BYTES>>>(Ep, vt16, ivp, out);
    }
}

// round 13
// speedup vs baseline: 1.1340x; 1.0218x over previous
#include <cuda_runtime.h>
#include <cuda_fp16.h>
#include <cstdint>
#include <math.h>

// ---------------------------------------------------------------------------
// Fixed problem: B=4, S=2048, D=DK=1024. M = B*S = 8192.
// R13: R12 algebra (QK^T = x M x^T + rank-1 bias terms) + overhead cuts:
//   - weight conversion and bias-dot vectors fused into one kernel
//   - inv[row] computed inside the AV epilogue (inv_rows kernel removed)
// GEMM engine = R11 (fp16 HMMA, in-chunk sw pipeline, 8 warps, 2 CTA/SM).
// ---------------------------------------------------------------------------
#define BATCH 4
#define SEQ   2048
#define DIM   1024
#define DKV   1024
#define MTOT  (BATCH * SEQ)

#define TILE  128
#define KC    64          // fp16 elements per K-chunk (128B rows, SW128)

// ---------------- scratch (device globals; no allocation) -------------------
__device__ __half g_x16[(size_t)MTOT * DIM];
__device__ __half g_wq16[(size_t)DIM * DKV];             // Wq fp16 (plain)
__device__ __half g_wk16[(size_t)DIM * DKV];             // Wk fp16 (plain)
__device__ __half g_wvt16[(size_t)DKV * DIM];            // Wv^T fp16
__device__ __half g_mt16[(size_t)DIM * DIM];             // (Wq Wk^T)^T fp16
__device__ __half g_g16[(size_t)MTOT * DIM];             // G = x M
__device__ __half g_vt16[(size_t)MTOT * DKV];            // V^T per batch
__device__ __half g_E [(size_t)BATCH * SEQ * SEQ];       // exp(scores), fp16
__device__ float  g_rsum[(size_t)MTOT * 16];
__device__ float  g_wu[DIM];                             // Wq bk
__device__ float  g_wt[DIM];                             // Wk bq
__device__ float  g_u [(size_t)MTOT];                    // x (Wq bk)
__device__ float  g_t [(size_t)MTOT];                    // x (Wk bq)
__device__ float  g_c [1];                               // bq . bk

// ---------------- PTX helpers ----------------------------------------------
static __device__ __forceinline__ uint32_t smem_u32(const void* p) {
    uint32_t a;
    asm("{ .reg .u64 t; cvta.to.shared.u64 t, %1; cvt.u32.u64 %0, t; }" : "=r"(a) : "l"(p));
    return a;
}
static __device__ __forceinline__ void cp16(uint32_t dst, const void* src) {
    asm volatile("cp.async.cg.shared.global [%0], [%1], 16;" :: "r"(dst), "l"(src) : "memory");
}
static __device__ __forceinline__ void cp_commit() {
    asm volatile("cp.async.commit_group;" ::: "memory");
}
static __device__ __forceinline__ void ldsm4(uint32_t* r, uint32_t addr) {
    asm volatile("ldmatrix.sync.aligned.m8n8.x4.shared.b16 {%0,%1,%2,%3}, [%4];"
                 : "=r"(r[0]), "=r"(r[1]), "=r"(r[2]), "=r"(r[3]) : "r"(addr));
}
static __device__ __forceinline__ void mma16816(float* c, const uint32_t* a, const uint32_t* b) {
    asm volatile(
        "mma.sync.aligned.m16n8k16.row.col.f32.f16.f16.f32 "
        "{%0,%1,%2,%3}, {%4,%5,%6,%7}, {%8,%9}, {%0,%1,%2,%3};"
        : "+f"(c[0]), "+f"(c[1]), "+f"(c[2]), "+f"(c[3])
        : "r"(a[0]), "r"(a[1]), "r"(a[2]), "r"(a[3]), "r"(b[0]), "r"(b[1]));
}
static __device__ __forceinline__ uint32_t sw128(uint32_t off) {
    return off ^ ((off >> 3) & 0x70);
}

// Stage (32KB): A @0 (16KB), B @16KB. 128 rows x 128B, SW128 swizzle.
#define STAGE_BYTES 32768
#define NSTAGE      3
#define SMEM_BYTES  (1024 + NSTAGE * STAGE_BYTES)

static __device__ __forceinline__ void load_chunk(
    const __half* A, const __half* B, int K,
    int m0, int n0, int koff, uint32_t stage, int tid)
{
    #pragma unroll
    for (int j = 0; j < 4; j++) {
        int id = tid + j * 256;                 // 0..1023
        int r  = id >> 3;                       // 0..127
        int cb = (id & 7) << 4;                 // byte col in 128B row
        uint32_t sw = sw128((uint32_t)((r << 7) + cb));
        cp16(stage +         sw, A + (long)(m0 + r) * K + koff + (cb >> 1));
        cp16(stage + 16384 + sw, B + (long)(n0 + r) * K + koff + (cb >> 1));
    }
    cp_commit();
}

// Shared prolog + pipelined mainloop + accumulator->tile spill (R11 engine).
#define GEMM_BODY(Aptr, Bptr, Kdim)                                              \
    extern __shared__ char smraw[];                                              \
    const int tid = threadIdx.x;                                                 \
    const int wid = tid >> 5;                                                    \
    const int lid = tid & 31;                                                    \
    const int z   = blockIdx.z;                                                  \
    const int m0  = blockIdx.y * TILE;                                           \
    const int n0  = blockIdx.x * TILE;                                           \
    const uint32_t smb = (smem_u32(smraw) + 1023u) & ~1023u;                     \
    uint32_t stg[NSTAGE];                                                        \
    _Pragma("unroll")                                                            \
    for (int s = 0; s < NSTAGE; s++) stg[s] = smb + s * STAGE_BYTES;             \
    const int wm = (wid >> 2) * 64;                                              \
    const int wn = (wid & 3) * 32;                                               \
    const int aRow  = wm + (lid & 15);                                           \
    const int aColB = (lid >> 4) << 4;                                           \
    const int bRow  = wn + (((lid >> 4) & 1) << 3) + (lid & 7);                  \
    const int bColB = ((lid >> 3) & 1) << 4;                                     \
    uint32_t aOff[4], bOff[2];                                                   \
    _Pragma("unroll")                                                            \
    for (int t = 0; t < 4; t++)                                                  \
        aOff[t] = sw128((uint32_t)((aRow + t * 16) << 7) + aColB);               \
    _Pragma("unroll")                                                            \
    for (int t = 0; t < 2; t++)                                                  \
        bOff[t] = sw128((uint32_t)((bRow + t * 16) << 7) + bColB) + 16384;       \
    float acc[4][4][4];                                                          \
    _Pragma("unroll")                                                            \
    for (int mi = 0; mi < 4; mi++)                                               \
        _Pragma("unroll")                                                        \
        for (int ni = 0; ni < 4; ni++)                                           \
            _Pragma("unroll")                                                    \
            for (int r = 0; r < 4; r++) acc[mi][ni][r] = 0.0f;                   \
    uint32_t fa[2][4], fb[2][8];                                                 \
    const int NC = (Kdim) / KC;                                                  \
    load_chunk((Aptr), (Bptr), (Kdim), m0, n0, 0, stg[0], tid);                  \
    load_chunk((Aptr), (Bptr), (Kdim), m0, n0, KC, stg[1], tid);                 \
    uint32_t cur = stg[0];                                                       \
    int nxt = 2;                                                                 \
    for (int i = 0; i < NC; i++) {                                               \
        asm volatile("cp.async.wait_group 1;" ::: "memory");                     \
        __syncthreads();                                                         \
        if (i + 2 < NC)                                                          \
            load_chunk((Aptr), (Bptr), (Kdim), m0, n0, (i + 2) * KC, stg[nxt], tid); \
        else                                                                     \
            cp_commit();                                                         \
        ldsm4(&fb[0][0], cur + bOff[0]);                                         \
        ldsm4(&fb[0][4], cur + bOff[1]);                                         \
        ldsm4(fa[0],     cur + aOff[0]);                                         \
        _Pragma("unroll")                                                        \
        for (int kk = 0; kk < 4; kk++) {                                         \
            const uint32_t xc = (uint32_t)(kk << 5);                             \
            const uint32_t xn = (uint32_t)((kk + 1) << 5);                       \
            _Pragma("unroll")                                                    \
            for (int mi = 0; mi < 4; mi++) {                                     \
                const int p  = (kk * 4 + mi) & 1;                                \
                const int np = p ^ 1;                                            \
                if (mi < 3) {                                                    \
                    ldsm4(fa[np], cur + (aOff[mi + 1] ^ xc));                     \
                } else if (kk < 3) {                                             \
                    ldsm4(&fb[(kk + 1) & 1][0], cur + (bOff[0] ^ xn));           \
                    ldsm4(&fb[(kk + 1) & 1][4], cur + (bOff[1] ^ xn));           \
                    ldsm4(fa[np], cur + (aOff[0] ^ xn));                         \
                }                                                                \
                uint32_t* B = fb[kk & 1];                                        \
                mma16816(acc[mi][0], fa[p], B + 0);                              \
                mma16816(acc[mi][1], fa[p], B + 2);                              \
                mma16816(acc[mi][2], fa[p], B + 4);                              \
                mma16816(acc[mi][3], fa[p], B + 6);                              \
            }                                                                    \
        }                                                                        \
        cur = stg[(i + 1) % NSTAGE];                                             \
        nxt = (nxt + 1) % NSTAGE;                                                \
    }                                                                            \
    __syncthreads();                                                             \
    float* tile = (float*)(smraw + (smb - smem_u32(smraw)));                     \
    {                                                                            \
        const int r0 = lid >> 2;                                                 \
        const int c0 = (lid & 3) * 2;                                            \
        _Pragma("unroll")                                                        \
        for (int mi = 0; mi < 4; mi++)                                           \
            _Pragma("unroll")                                                    \
            for (int ni = 0; ni < 4; ni++) {                                     \
                int m = wm + mi * 16 + r0;                                       \
                int n = wn + ni * 8 + c0;                                        \
                tile[m * 129 + n]           = acc[mi][ni][0];                    \
                tile[m * 129 + n + 1]       = acc[mi][ni][1];                    \
                tile[(m + 8) * 129 + n]     = acc[mi][ni][2];                    \
                tile[(m + 8) * 129 + n + 1] = acc[mi][ni][3];                    \
            }                                                                    \
    }                                                                            \
    __syncthreads();

// ---------------- M = Wq Wk^T, written transposed fp16 ----------------------
__global__ void __launch_bounds__(256, 2)
gemm_wm(const __half* __restrict__ Wq, const __half* __restrict__ Wk,
        __half* __restrict__ Mt)
{
    GEMM_BODY(Wq, Wk, DIM)
    (void)z;
    for (int idx = tid; idx < TILE * TILE; idx += 256) {
        int n = idx >> 7, mm = idx & 127;
        Mt[(long)(n0 + n) * DIM + m0 + mm] = __float2half(tile[mm * 129 + n]);
    }
}

// ---------------- proj: z=0: G = x M (plain); z=1: Vt = (x Wv + bv)^T -------
__global__ void __launch_bounds__(256, 2)
gemm_proj(const __half* __restrict__ A, const __half* __restrict__ Bmt,
          const __half* __restrict__ Bwv, const float* __restrict__ bv,
          __half* __restrict__ oG, __half* __restrict__ oVt)
{
    GEMM_BODY(A, (blockIdx.z == 0 ? Bmt : Bwv), DIM)

    if (z == 0) {
        for (int idx = tid; idx < TILE * TILE; idx += 256) {
            int r = idx >> 7, c = idx & 127;
            oG[(long)(m0 + r) * DKV + n0 + c] = __float2half(tile[r * 129 + c]);
        }
    } else {
        const int b = m0 >> 11, seq0 = m0 & 2047;
        for (int idx = tid; idx < TILE * TILE; idx += 256) {
            int n = idx >> 7, mm = idx & 127;
            float v = tile[mm * 129 + n] + bv[n0 + n];
            oVt[(long)b * DKV * SEQ + (long)(n0 + n) * SEQ + seq0 + mm] = __float2half(v);
        }
    }
}

// ---------------- scores: E = exp((G x^T + u + t + c)/32 + mask) fp16 -------
__global__ void __launch_bounds__(256, 2)
gemm_scores(const __half* __restrict__ G, const __half* __restrict__ X,
            const float* __restrict__ mask, const float* __restrict__ u,
            const float* __restrict__ tv, const float* __restrict__ cp,
            __half* __restrict__ Eh, float* __restrict__ rsum)
{
    GEMM_BODY(G + (long)blockIdx.z * SEQ * DKV,
              X + (long)blockIdx.z * SEQ * DIM, DIM)

    const long bo = (long)z * SEQ * SEQ;
    const float cv = cp[0];
    for (int idx = tid; idx < TILE * TILE; idx += 256) {
        int r = idx >> 7, c = idx & 127;
        long o = bo + (long)(m0 + r) * SEQ + n0 + c;
        float s = tile[r * 129 + c] + u[(z << 11) + m0 + r] + tv[(z << 11) + n0 + c] + cv;
        float e = __expf(__fmaf_rn(s, 0.03125f, mask[o]));
        __half eh = __float2half(e);
        Eh[o] = eh;
        tile[r * 129 + c] = __half2float(eh);
    }
    __syncthreads();
    if (tid < 128) {
        float s = 0.0f;
        #pragma unroll 8
        for (int c = 0; c < 128; c++) s += tile[tid * 129 + c];
        rsum[((long)(z << 11) + m0 + tid) * 16 + blockIdx.x] = s;
    }
}

// ---------------- AV GEMM: out = inv[row] * (E @ V); inv from rsum ----------
__global__ void __launch_bounds__(256, 2)
gemm_av(const __half* __restrict__ E, const __half* __restrict__ Vt,
        const float* __restrict__ rsum, float* __restrict__ outF)
{
    GEMM_BODY(E + (long)blockIdx.z * SEQ * SEQ,
              Vt + (long)blockIdx.z * DKV * SEQ, SEQ)

    // per-row 1/sum computed locally from the 16 rsum partials (L2-hot)
    float* sinv = tile + 128 * 129;
    if (tid < 128) {
        const float* rs = rsum + ((long)((z << 11) + m0 + tid)) * 16;
        float s = 0.0f;
        #pragma unroll
        for (int t = 0; t < 16; t++) s += rs[t];
        sinv[tid] = 1.0f / s;
    }
    __syncthreads();

    const long bo = (long)z * SEQ * DKV;
    for (int idx = tid; idx < TILE * TILE; idx += 256) {
        int r = idx >> 7, c = idx & 127;
        outF[bo + (long)(m0 + r) * DKV + n0 + c] = tile[r * 129 + c] * sinv[r];
    }
}

// ---------------- x -> fp16 --------------------------------------------------
__global__ void __launch_bounds__(256)
conv_x(const float4* __restrict__ in, __half2* __restrict__ out, int n4)
{
    int i = blockIdx.x * 256 + threadIdx.x;
    if (i >= n4) return;
    float4 v = in[i];
    out[i * 2]     = __floats2half2_rn(v.x, v.y);
    out[i * 2 + 1] = __floats2half2_rn(v.z, v.w);
}

// ---------------- fused: Wq/Wk -> fp16 + bias-dot vectors + c ---------------
// grid (DIM, 2): block = one weight row. y=0: Wq row, dot with bk -> wu.
//                                       y=1: Wk row, dot with bq -> wt.
__global__ void __launch_bounds__(256)
convw_dot(const float* __restrict__ Wq, const float* __restrict__ Wk,
          const float* __restrict__ bq, const float* __restrict__ bk,
          __half* __restrict__ oq, __half* __restrict__ ok,
          float* __restrict__ wu, float* __restrict__ wt, float* __restrict__ cp)
{
    __shared__ float red[256];
    const int d = blockIdx.x;
    const int t = threadIdx.x;
    const float* W  = blockIdx.y ? Wk : Wq;
    const float* bv = blockIdx.y ? bq : bk;
    __half* o       = blockIdx.y ? ok : oq;
    float* dst      = blockIdx.y ? wt : wu;

    float4 v = ((const float4*)(W + (long)d * DKV))[t];
    float4 b = ((const float4*)bv)[t];
    __half2* o2 = (__half2*)(o + (long)d * DKV);
    o2[t * 2]     = __floats2half2_rn(v.x, v.y);
    o2[t * 2 + 1] = __floats2half2_rn(v.z, v.w);

    red[t] = v.x * b.x + v.y * b.y + v.z * b.z + v.w * b.w;
    __syncthreads();
    #pragma unroll
    for (int k = 128; k > 0; k >>= 1) {
        if (t < k) red[t] += red[t + k];
        __syncthreads();
    }
    if (t == 0) dst[d] = red[0];

    if (blockIdx.x == 0 && blockIdx.y == 0) {
        float4 q = ((const float4*)bq)[t];
        float4 k = ((const float4*)bk)[t];
        __syncthreads();
        red[t] = q.x * k.x + q.y * k.y + q.z * k.z + q.w * k.w;
        __syncthreads();
        #pragma unroll
        for (int kk = 128; kk > 0; kk >>= 1) {
            if (t < kk) red[t] += red[t + kk];
            __syncthreads();
        }
        if (t == 0) cp[0] = red[0];
    }
}

// ---------------- transpose + convert Wv ------------------------------------
__global__ void __launch_bounds__(256)
tconv_wv(const float* __restrict__ in, __half* __restrict__ out)
{
    __shared__ float t[32][33];
    const int bx = blockIdx.x * 32, by = blockIdx.y * 32;
    const int tx = threadIdx.x, ty = threadIdx.y;       // block (32,8)
    #pragma unroll
    for (int k = 0; k < 32; k += 8)
        t[ty + k][tx] = in[(long)(by + ty + k) * DKV + bx + tx];
    __syncthreads();
    #pragma unroll
    for (int k = 0; k < 32; k += 8)
        out[(long)(bx + ty + k) * DIM + by + tx] = __float2half(t[tx][ty + k]);
}

// ---------------- u = x wu, t = x wt (one warp per row) ---------------------
__global__ void __launch_bounds__(256)
ut_gemv(const __half* __restrict__ x16, const float* __restrict__ wu,
        const float* __restrict__ wt, float* __restrict__ u, float* __restrict__ t)
{
    int q = blockIdx.x * 8 + (threadIdx.x >> 5);
    int l = threadIdx.x & 31;
    const __half2* xr = (const __half2*)(x16 + (long)q * DIM);
    const float2* wu2 = (const float2*)wu;
    const float2* wt2 = (const float2*)wt;
    float su = 0.0f, st = 0.0f;
    for (int i = l; i < DIM / 2; i += 32) {
        float2 xf = __half22float2(xr[i]);
        float2 a = wu2[i], b = wt2[i];
        su += xf.x * a.x + xf.y * a.y;
        st += xf.x * b.x + xf.y * b.y;
    }
    #pragma unroll
    for (int s = 16; s > 0; s >>= 1) {
        su += __shfl_down_sync(0xffffffff, su, s);
        st += __shfl_down_sync(0xffffffff, st, s);
    }
    if (l == 0) { u[q] = su; t[q] = st; }
}

// ---------------------------------------------------------------------------
extern "C" void kernel_launch(void* const* d_in, const int* in_sizes, int n_in,
                              void* d_out, int out_size)
{
    const float* x    = (const float*)d_in[0];
    const float* mask = (const float*)d_in[1];
    const float* Wq   = (const float*)d_in[2];
    const float* bq   = (const float*)d_in[3];
    const float* Wk   = (const float*)d_in[4];
    const float* bk   = (const float*)d_in[5];
    const float* Wv   = (const float*)d_in[6];
    const float* bv   = (const float*)d_in[7];
    float* out = (float*)d_out;

    __half *x16, *wq16, *wk16, *wvt16, *mt16, *g16, *vt16, *Ep;
    float *rsp, *wup, *wtp, *up, *tp, *cpv;
    cudaGetSymbolAddress((void**)&x16,   g_x16);
    cudaGetSymbolAddress((void**)&wq16,  g_wq16);
    cudaGetSymbolAddress((void**)&wk16,  g_wk16);
    cudaGetSymbolAddress((void**)&wvt16, g_wvt16);
    cudaGetSymbolAddress((void**)&mt16,  g_mt16);
    cudaGetSymbolAddress((void**)&g16,   g_g16);
    cudaGetSymbolAddress((void**)&vt16,  g_vt16);
    cudaGetSymbolAddress((void**)&Ep,    g_E);
    cudaGetSymbolAddress((void**)&rsp,   g_rsum);
    cudaGetSymbolAddress((void**)&wup,   g_wu);
    cudaGetSymbolAddress((void**)&wtp,   g_wt);
    cudaGetSymbolAddress((void**)&up,    g_u);
    cudaGetSymbolAddress((void**)&tp,    g_t);
    cudaGetSymbolAddress((void**)&cpv,   g_c);

    cudaFuncSetAttribute(gemm_wm,     cudaFuncAttributeMaxDynamicSharedMemorySize, SMEM_BYTES);
    cudaFuncSetAttribute(gemm_proj,   cudaFuncAttributeMaxDynamicSharedMemorySize, SMEM_BYTES);
    cudaFuncSetAttribute(gemm_scores, cudaFuncAttributeMaxDynamicSharedMemorySize, SMEM_BYTES);
    cudaFuncSetAttribute(gemm_av,     cudaFuncAttributeMaxDynamicSharedMemorySize, SMEM_BYTES);

    // 1) conversions + bias-vector prep (fused)
    {
        int n4x = MTOT * DIM / 4;
        conv_x<<<n4x / 256, 256>>>((const float4*)x, (__half2*)x16, n4x);
        dim3 gw(DIM, 2);
        convw_dot<<<gw, 256>>>(Wq, Wk, bq, bk, wq16, wk16, wup, wtp, cpv);
        dim3 tb(32, 8), tg(32, 32);
        tconv_wv<<<tg, tb>>>(Wv, wvt16);
        ut_gemv<<<MTOT / 8, 256>>>(x16, wup, wtp, up, tp);
    }

    dim3 blk(256);

    // 2) M = Wq Wk^T (transposed fp16 out)
    {
        dim3 g(DIM / TILE, DIM / TILE, 1);
        gemm_wm<<<g, blk, SMEM_BYTES>>>(wq16, wk16, mt16);
    }

    // 3) z=0: G = x M;  z=1: Vt = (x Wv + bv)^T
    {
        dim3 g(DKV / TILE, MTOT / TILE, 2);
        gemm_proj<<<g, blk, SMEM_BYTES>>>(x16, mt16, wvt16, bv, g16, vt16);
    }

    // 4) E = exp((G x^T + u + t + c)/32 + mask) fp16, per-tile row sums
    {
        dim3 g(SEQ / TILE, SEQ / TILE, BATCH);
        gemm_scores<<<g, blk, SMEM_BYTES>>>(g16, x16, mask, up, tp, cpv, Ep, rsp);
    }

    // 5) out = inv * (E @ V), inv folded into epilogue
    {
        dim3 g(DKV / TILE, SEQ / TILE, BATCH);
        gemm_av<<<g, blk, SMEM_BYTES>>>(Ep, vt16, rsp, out);
    }
}

// round 14
// speedup vs baseline: 1.1788x; 1.0395x over previous
#include <cuda_runtime.h>
#include <cuda_fp16.h>
#include <cstdint>
#include <math.h>

// ---------------------------------------------------------------------------
// Fixed problem: B=4, S=2048, D=DK=1024. M = B*S = 8192.
// R14: softmax-invariance prune. scores = x M x^T + u 1^T + 1 t^T + c, but
// u[q] and c are constant along the softmax axis -> cancel in normalization.
// Only t[p] = x_p . (Wk bq) kept, computed inside conv_x (fused). ut_gemv
// deleted. GEMM engine = R11 (fp16 HMMA, in-chunk sw pipeline, 2 CTA/SM).
// ---------------------------------------------------------------------------
#define BATCH 4
#define SEQ   2048
#define DIM   1024
#define DKV   1024
#define MTOT  (BATCH * SEQ)

#define TILE  128
#define KC    64          // fp16 elements per K-chunk (128B rows, SW128)

// ---------------- scratch (device globals; no allocation) -------------------
__device__ __half g_x16[(size_t)MTOT * DIM];
__device__ __half g_wq16[(size_t)DIM * DKV];             // Wq fp16 (plain)
__device__ __half g_wk16[(size_t)DIM * DKV];             // Wk fp16 (plain)
__device__ __half g_wvt16[(size_t)DKV * DIM];            // Wv^T fp16
__device__ __half g_mt16[(size_t)DIM * DIM];             // (Wq Wk^T)^T fp16
__device__ __half g_g16[(size_t)MTOT * DIM];             // G = x M
__device__ __half g_vt16[(size_t)MTOT * DKV];            // V^T per batch
__device__ __half g_E [(size_t)BATCH * SEQ * SEQ];       // exp(scores), fp16
__device__ float  g_rsum[(size_t)MTOT * 16];
__device__ float  g_wt[DIM];                             // Wk bq
__device__ float  g_t [(size_t)MTOT];                    // x (Wk bq)

// ---------------- PTX helpers ----------------------------------------------
static __device__ __forceinline__ uint32_t smem_u32(const void* p) {
    uint32_t a;
    asm("{ .reg .u64 t; cvta.to.shared.u64 t, %1; cvt.u32.u64 %0, t; }" : "=r"(a) : "l"(p));
    return a;
}
static __device__ __forceinline__ void cp16(uint32_t dst, const void* src) {
    asm volatile("cp.async.cg.shared.global [%0], [%1], 16;" :: "r"(dst), "l"(src) : "memory");
}
static __device__ __forceinline__ void cp_commit() {
    asm volatile("cp.async.commit_group;" ::: "memory");
}
static __device__ __forceinline__ void ldsm4(uint32_t* r, uint32_t addr) {
    asm volatile("ldmatrix.sync.aligned.m8n8.x4.shared.b16 {%0,%1,%2,%3}, [%4];"
                 : "=r"(r[0]), "=r"(r[1]), "=r"(r[2]), "=r"(r[3]) : "r"(addr));
}
static __device__ __forceinline__ void mma16816(float* c, const uint32_t* a, const uint32_t* b) {
    asm volatile(
        "mma.sync.aligned.m16n8k16.row.col.f32.f16.f16.f32 "
        "{%0,%1,%2,%3}, {%4,%5,%6,%7}, {%8,%9}, {%0,%1,%2,%3};"
        : "+f"(c[0]), "+f"(c[1]), "+f"(c[2]), "+f"(c[3])
        : "r"(a[0]), "r"(a[1]), "r"(a[2]), "r"(a[3]), "r"(b[0]), "r"(b[1]));
}
static __device__ __forceinline__ uint32_t sw128(uint32_t off) {
    return off ^ ((off >> 3) & 0x70);
}

// Stage (32KB): A @0 (16KB), B @16KB. 128 rows x 128B, SW128 swizzle.
#define STAGE_BYTES 32768
#define NSTAGE      3
#define SMEM_BYTES  (1024 + NSTAGE * STAGE_BYTES)

static __device__ __forceinline__ void load_chunk(
    const __half* A, const __half* B, int K,
    int m0, int n0, int koff, uint32_t stage, int tid)
{
    #pragma unroll
    for (int j = 0; j < 4; j++) {
        int id = tid + j * 256;                 // 0..1023
        int r  = id >> 3;                       // 0..127
        int cb = (id & 7) << 4;                 // byte col in 128B row
        uint32_t sw = sw128((uint32_t)((r << 7) + cb));
        cp16(stage +         sw, A + (long)(m0 + r) * K + koff + (cb >> 1));
        cp16(stage + 16384 + sw, B + (long)(n0 + r) * K + koff + (cb >> 1));
    }
    cp_commit();
}

// Shared prolog + pipelined mainloop + accumulator->tile spill (R11 engine).
#define GEMM_BODY(Aptr, Bptr, Kdim)                                              \
    extern __shared__ char smraw[];                                              \
    const int tid = threadIdx.x;                                                 \
    const int wid = tid >> 5;                                                    \
    const int lid = tid & 31;                                                    \
    const int z   = blockIdx.z;                                                  \
    const int m0  = blockIdx.y * TILE;                                           \
    const int n0  = blockIdx.x * TILE;                                           \
    const uint32_t smb = (smem_u32(smraw) + 1023u) & ~1023u;                     \
    uint32_t stg[NSTAGE];                                                        \
    _Pragma("unroll")                                                            \
    for (int s = 0; s < NSTAGE; s++) stg[s] = smb + s * STAGE_BYTES;             \
    const int wm = (wid >> 2) * 64;                                              \
    const int wn = (wid & 3) * 32;                                               \
    const int aRow  = wm + (lid & 15);                                           \
    const int aColB = (lid >> 4) << 4;                                           \
    const int bRow  = wn + (((lid >> 4) & 1) << 3) + (lid & 7);                  \
    const int bColB = ((lid >> 3) & 1) << 4;                                     \
    uint32_t aOff[4], bOff[2];                                                   \
    _Pragma("unroll")                                                            \
    for (int t = 0; t < 4; t++)                                                  \
        aOff[t] = sw128((uint32_t)((aRow + t * 16) << 7) + aColB);               \
    _Pragma("unroll")                                                            \
    for (int t = 0; t < 2; t++)                                                  \
        bOff[t] = sw128((uint32_t)((bRow + t * 16) << 7) + bColB) + 16384;       \
    float acc[4][4][4];                                                          \
    _Pragma("unroll")                                                            \
    for (int mi = 0; mi < 4; mi++)                                               \
        _Pragma("unroll")                                                        \
        for (int ni = 0; ni < 4; ni++)                                           \
            _Pragma("unroll")                                                    \
            for (int r = 0; r < 4; r++) acc[mi][ni][r] = 0.0f;                   \
    uint32_t fa[2][4], fb[2][8];                                                 \
    const int NC = (Kdim) / KC;                                                  \
    load_chunk((Aptr), (Bptr), (Kdim), m0, n0, 0, stg[0], tid);                  \
    load_chunk((Aptr), (Bptr), (Kdim), m0, n0, KC, stg[1], tid);                 \
    uint32_t cur = stg[0];                                                       \
    int nxt = 2;                                                                 \
    for (int i = 0; i < NC; i++) {                                               \
        asm volatile("cp.async.wait_group 1;" ::: "memory");                     \
        __syncthreads();                                                         \
        if (i + 2 < NC)                                                          \
            load_chunk((Aptr), (Bptr), (Kdim), m0, n0, (i + 2) * KC, stg[nxt], tid); \
        else                                                                     \
            cp_commit();                                                         \
        ldsm4(&fb[0][0], cur + bOff[0]);                                         \
        ldsm4(&fb[0][4], cur + bOff[1]);                                         \
        ldsm4(fa[0],     cur + aOff[0]);                                         \
        _Pragma("unroll")                                                        \
        for (int kk = 0; kk < 4; kk++) {                                         \
            const uint32_t xc = (uint32_t)(kk << 5);                             \
            const uint32_t xn = (uint32_t)((kk + 1) << 5);                       \
            _Pragma("unroll")                                                    \
            for (int mi = 0; mi < 4; mi++) {                                     \
                const int p  = (kk * 4 + mi) & 1;                                \
                const int np = p ^ 1;                                            \
                if (mi < 3) {                                                    \
                    ldsm4(fa[np], cur + (aOff[mi + 1] ^ xc));                     \
                } else if (kk < 3) {                                             \
                    ldsm4(&fb[(kk + 1) & 1][0], cur + (bOff[0] ^ xn));           \
                    ldsm4(&fb[(kk + 1) & 1][4], cur + (bOff[1] ^ xn));           \
                    ldsm4(fa[np], cur + (aOff[0] ^ xn));                         \
                }                                                                \
                uint32_t* B = fb[kk & 1];                                        \
                mma16816(acc[mi][0], fa[p], B + 0);                              \
                mma16816(acc[mi][1], fa[p], B + 2);                              \
                mma16816(acc[mi][2], fa[p], B + 4);                              \
                mma16816(acc[mi][3], fa[p], B + 6);                              \
            }                                                                    \
        }                                                                        \
        cur = stg[(i + 1) % NSTAGE];                                             \
        nxt = (nxt + 1) % NSTAGE;                                                \
    }                                                                            \
    __syncthreads();                                                             \
    float* tile = (float*)(smraw + (smb - smem_u32(smraw)));                     \
    {                                                                            \
        const int r0 = lid >> 2;                                                 \
        const int c0 = (lid & 3) * 2;                                            \
        _Pragma("unroll")                                                        \
        for (int mi = 0; mi < 4; mi++)                                           \
            _Pragma("unroll")                                                    \
            for (int ni = 0; ni < 4; ni++) {                                     \
                int m = wm + mi * 16 + r0;                                       \
                int n = wn + ni * 8 + c0;                                        \
                tile[m * 129 + n]           = acc[mi][ni][0];                    \
                tile[m * 129 + n + 1]       = acc[mi][ni][1];                    \
                tile[(m + 8) * 129 + n]     = acc[mi][ni][2];                    \
                tile[(m + 8) * 129 + n + 1] = acc[mi][ni][3];                    \
            }                                                                    \
    }                                                                            \
    __syncthreads();

// ---------------- M = Wq Wk^T, written transposed fp16 ----------------------
__global__ void __launch_bounds__(256, 2)
gemm_wm(const __half* __restrict__ Wq, const __half* __restrict__ Wk,
        __half* __restrict__ Mt)
{
    GEMM_BODY(Wq, Wk, DIM)
    (void)z;
    for (int idx = tid; idx < TILE * TILE; idx += 256) {
        int n = idx >> 7, mm = idx & 127;
        Mt[(long)(n0 + n) * DIM + m0 + mm] = __float2half(tile[mm * 129 + n]);
    }
}

// ---------------- proj: z=0: G = x M (plain); z=1: Vt = (x Wv + bv)^T -------
__global__ void __launch_bounds__(256, 2)
gemm_proj(const __half* __restrict__ A, const __half* __restrict__ Bmt,
          const __half* __restrict__ Bwv, const float* __restrict__ bv,
          __half* __restrict__ oG, __half* __restrict__ oVt)
{
    GEMM_BODY(A, (blockIdx.z == 0 ? Bmt : Bwv), DIM)

    if (z == 0) {
        for (int idx = tid; idx < TILE * TILE; idx += 256) {
            int r = idx >> 7, c = idx & 127;
            oG[(long)(m0 + r) * DKV + n0 + c] = __float2half(tile[r * 129 + c]);
        }
    } else {
        const int b = m0 >> 11, seq0 = m0 & 2047;
        for (int idx = tid; idx < TILE * TILE; idx += 256) {
            int n = idx >> 7, mm = idx & 127;
            float v = tile[mm * 129 + n] + bv[n0 + n];
            oVt[(long)b * DKV * SEQ + (long)(n0 + n) * SEQ + seq0 + mm] = __float2half(v);
        }
    }
}

// ---------------- scores: E = exp((G x^T + t[p]) / 32 + mask) fp16 ----------
__global__ void __launch_bounds__(256, 2)
gemm_scores(const __half* __restrict__ G, const __half* __restrict__ X,
            const float* __restrict__ mask, const float* __restrict__ tv,
            __half* __restrict__ Eh, float* __restrict__ rsum)
{
    GEMM_BODY(G + (long)blockIdx.z * SEQ * DKV,
              X + (long)blockIdx.z * SEQ * DIM, DIM)

    const long bo = (long)z * SEQ * SEQ;
    for (int idx = tid; idx < TILE * TILE; idx += 256) {
        int r = idx >> 7, c = idx & 127;
        long o = bo + (long)(m0 + r) * SEQ + n0 + c;
        float s = tile[r * 129 + c] + tv[(z << 11) + n0 + c];
        float e = __expf(__fmaf_rn(s, 0.03125f, mask[o]));
        __half eh = __float2half(e);
        Eh[o] = eh;
        tile[r * 129 + c] = __half2float(eh);
    }
    __syncthreads();
    if (tid < 128) {
        float s = 0.0f;
        #pragma unroll 8
        for (int c = 0; c < 128; c++) s += tile[tid * 129 + c];
        rsum[((long)(z << 11) + m0 + tid) * 16 + blockIdx.x] = s;
    }
}

// ---------------- AV GEMM: out = inv[row] * (E @ V); inv from rsum ----------
__global__ void __launch_bounds__(256, 2)
gemm_av(const __half* __restrict__ E, const __half* __restrict__ Vt,
        const float* __restrict__ rsum, float* __restrict__ outF)
{
    GEMM_BODY(E + (long)blockIdx.z * SEQ * SEQ,
              Vt + (long)blockIdx.z * DKV * SEQ, SEQ)

    // per-row 1/sum computed locally from the 16 rsum partials (L2-hot)
    float* sinv = tile + 128 * 129;
    if (tid < 128) {
        const float* rs = rsum + ((long)((z << 11) + m0 + tid)) * 16;
        float s = 0.0f;
        #pragma unroll
        for (int t = 0; t < 16; t++) s += rs[t];
        sinv[tid] = 1.0f / s;
    }
    __syncthreads();

    const long bo = (long)z * SEQ * DKV;
    for (int idx = tid; idx < TILE * TILE; idx += 256) {
        int r = idx >> 7, c = idx & 127;
        outF[bo + (long)(m0 + r) * DKV + n0 + c] = tile[r * 129 + c] * sinv[r];
    }
}

// ---------------- fused: x -> fp16 + t[row] = x_row . wt --------------------
// one block per row: 256 threads x 1 float4 = 1024 floats
__global__ void __launch_bounds__(256)
conv_x_t(const float* __restrict__ x, const float* __restrict__ wt,
         __half* __restrict__ x16, float* __restrict__ tOut)
{
    __shared__ float red[256];
    const int row = blockIdx.x;
    const int t = threadIdx.x;
    float4 v = ((const float4*)(x + (long)row * DIM))[t];
    float4 w = ((const float4*)wt)[t];
    __half2* o2 = (__half2*)(x16 + (long)row * DIM);
    o2[t * 2]     = __floats2half2_rn(v.x, v.y);
    o2[t * 2 + 1] = __floats2half2_rn(v.z, v.w);
    red[t] = v.x * w.x + v.y * w.y + v.z * w.z + v.w * w.w;
    __syncthreads();
    #pragma unroll
    for (int k = 128; k > 0; k >>= 1) {
        if (t < k) red[t] += red[t + k];
        __syncthreads();
    }
    if (t == 0) tOut[row] = red[0];
}

// ---------------- fused: Wq/Wk -> fp16 + wt = Wk bq -------------------------
// grid (DIM, 2): y=0 converts Wq row; y=1 converts Wk row + dot with bq.
__global__ void __launch_bounds__(256)
convw_dot(const float* __restrict__ Wq, const float* __restrict__ Wk,
          const float* __restrict__ bq,
          __half* __restrict__ oq, __half* __restrict__ ok,
          float* __restrict__ wt)
{
    __shared__ float red[256];
    const int d = blockIdx.x;
    const int t = threadIdx.x;
    const float* W = blockIdx.y ? Wk : Wq;
    __half* o      = blockIdx.y ? ok : oq;

    float4 v = ((const float4*)(W + (long)d * DKV))[t];
    __half2* o2 = (__half2*)(o + (long)d * DKV);
    o2[t * 2]     = __floats2half2_rn(v.x, v.y);
    o2[t * 2 + 1] = __floats2half2_rn(v.z, v.w);

    if (blockIdx.y) {
        float4 b = ((const float4*)bq)[t];
        red[t] = v.x * b.x + v.y * b.y + v.z * b.z + v.w * b.w;
        __syncthreads();
        #pragma unroll
        for (int k = 128; k > 0; k >>= 1) {
            if (t < k) red[t] += red[t + k];
            __syncthreads();
        }
        if (t == 0) wt[d] = red[0];
    }
}

// ---------------- transpose + convert Wv ------------------------------------
__global__ void __launch_bounds__(256)
tconv_wv(const float* __restrict__ in, __half* __restrict__ out)
{
    __shared__ float t[32][33];
    const int bx = blockIdx.x * 32, by = blockIdx.y * 32;
    const int tx = threadIdx.x, ty = threadIdx.y;       // block (32,8)
    #pragma unroll
    for (int k = 0; k < 32; k += 8)
        t[ty + k][tx] = in[(long)(by + ty + k) * DKV + bx + tx];
    __syncthreads();
    #pragma unroll
    for (int k = 0; k < 32; k += 8)
        out[(long)(bx + ty + k) * DIM + by + tx] = __float2half(t[tx][ty + k]);
}

// ---------------------------------------------------------------------------
extern "C" void kernel_launch(void* const* d_in, const int* in_sizes, int n_in,
                              void* d_out, int out_size)
{
    const float* x    = (const float*)d_in[0];
    const float* mask = (const float*)d_in[1];
    const float* Wq   = (const float*)d_in[2];
    const float* bq   = (const float*)d_in[3];
    const float* Wk   = (const float*)d_in[4];
    const float* bk   = (const float*)d_in[5];
    const float* Wv   = (const float*)d_in[6];
    const float* bv   = (const float*)d_in[7];
    float* out = (float*)d_out;
    (void)bk;   // cancels in softmax (u[q], c terms)

    __half *x16, *wq16, *wk16, *wvt16, *mt16, *g16, *vt16, *Ep;
    float *rsp, *wtp, *tp;
    cudaGetSymbolAddress((void**)&x16,   g_x16);
    cudaGetSymbolAddress((void**)&wq16,  g_wq16);
    cudaGetSymbolAddress((void**)&wk16,  g_wk16);
    cudaGetSymbolAddress((void**)&wvt16, g_wvt16);
    cudaGetSymbolAddress((void**)&mt16,  g_mt16);
    cudaGetSymbolAddress((void**)&g16,   g_g16);
    cudaGetSymbolAddress((void**)&vt16,  g_vt16);
    cudaGetSymbolAddress((void**)&Ep,    g_E);
    cudaGetSymbolAddress((void**)&rsp,   g_rsum);
    cudaGetSymbolAddress((void**)&wtp,   g_wt);
    cudaGetSymbolAddress((void**)&tp,    g_t);

    cudaFuncSetAttribute(gemm_wm,     cudaFuncAttributeMaxDynamicSharedMemorySize, SMEM_BYTES);
    cudaFuncSetAttribute(gemm_proj,   cudaFuncAttributeMaxDynamicSharedMemorySize, SMEM_BYTES);
    cudaFuncSetAttribute(gemm_scores, cudaFuncAttributeMaxDynamicSharedMemorySize, SMEM_BYTES);
    cudaFuncSetAttribute(gemm_av,     cudaFuncAttributeMaxDynamicSharedMemorySize, SMEM_BYTES);

    // 1) weight conversion + wt = Wk bq; then x conversion fused with t = x wt
    {
        dim3 gw(DIM, 2);
        convw_dot<<<gw, 256>>>(Wq, Wk, bq, wq16, wk16, wtp);
        dim3 tb(32, 8), tg(32, 32);
        tconv_wv<<<tg, tb>>>(Wv, wvt16);
        conv_x_t<<<MTOT, 256>>>(x, wtp, x16, tp);
    }

    dim3 blk(256);

    // 2) M = Wq Wk^T (transposed fp16 out)
    {
        dim3 g(DIM / TILE, DIM / TILE, 1);
        gemm_wm<<<g, blk, SMEM_BYTES>>>(wq16, wk16, mt16);
    }

    // 3) z=0: G = x M;  z=1: Vt = (x Wv + bv)^T
    {
        dim3 g(DKV / TILE, MTOT / TILE, 2);
        gemm_proj<<<g, blk, SMEM_BYTES>>>(x16, mt16, wvt16, bv, g16, vt16);
    }

    // 4) E = exp((G x^T + t)/32 + mask) fp16, per-tile row sums
    {
        dim3 g(SEQ / TILE, SEQ / TILE, BATCH);
        gemm_scores<<<g, blk, SMEM_BYTES>>>(g16, x16, mask, tp, Ep, rsp);
    }

    // 5) out = inv * (E @ V), inv folded into epilogue
    {
        dim3 g(DKV / TILE, SEQ / TILE, BATCH);
        gemm_av<<<g, blk, SMEM_BYTES>>>(Ep, vt16, rsp, out);
    }
}

// round 15
// speedup vs baseline: 1.1858x; 1.0059x over previous
#include <cuda_runtime.h>
#include <cuda_fp16.h>
#include <cstdint>
#include <math.h>

// ---------------------------------------------------------------------------
// Fixed problem: B=4, S=2048, D=DK=1024. M = B*S = 8192.
// R15: R14 + split-K gemm_wm (grid 8x8x4, fp32 partials + tiny reduce) to fix
// the 64-CTA underutilization. Engine/algebra otherwise frozen.
// ---------------------------------------------------------------------------
#define BATCH 4
#define SEQ   2048
#define DIM   1024
#define DKV   1024
#define MTOT  (BATCH * SEQ)

#define TILE  128
#define KC    64          // fp16 elements per K-chunk (128B rows, SW128)
#define WMSPLIT 4
#define WMKLEN  (DIM / WMSPLIT)   // 256

// ---------------- scratch (device globals; no allocation) -------------------
__device__ __half g_x16[(size_t)MTOT * DIM];
__device__ __half g_wq16[(size_t)DIM * DKV];             // Wq fp16 (plain)
__device__ __half g_wk16[(size_t)DIM * DKV];             // Wk fp16 (plain)
__device__ __half g_wvt16[(size_t)DKV * DIM];            // Wv^T fp16
__device__ __half g_mt16[(size_t)DIM * DIM];             // (Wq Wk^T)^T fp16
__device__ float  g_mpart[(size_t)WMSPLIT * DIM * DIM];  // split-K partials (T)
__device__ __half g_g16[(size_t)MTOT * DIM];             // G = x M
__device__ __half g_vt16[(size_t)MTOT * DKV];            // V^T per batch
__device__ __half g_E [(size_t)BATCH * SEQ * SEQ];       // exp(scores), fp16
__device__ float  g_rsum[(size_t)MTOT * 16];
__device__ float  g_wt[DIM];                             // Wk bq
__device__ float  g_t [(size_t)MTOT];                    // x (Wk bq)

// ---------------- PTX helpers ----------------------------------------------
static __device__ __forceinline__ uint32_t smem_u32(const void* p) {
    uint32_t a;
    asm("{ .reg .u64 t; cvta.to.shared.u64 t, %1; cvt.u32.u64 %0, t; }" : "=r"(a) : "l"(p));
    return a;
}
static __device__ __forceinline__ void cp16(uint32_t dst, const void* src) {
    asm volatile("cp.async.cg.shared.global [%0], [%1], 16;" :: "r"(dst), "l"(src) : "memory");
}
static __device__ __forceinline__ void cp_commit() {
    asm volatile("cp.async.commit_group;" ::: "memory");
}
static __device__ __forceinline__ void ldsm4(uint32_t* r, uint32_t addr) {
    asm volatile("ldmatrix.sync.aligned.m8n8.x4.shared.b16 {%0,%1,%2,%3}, [%4];"
                 : "=r"(r[0]), "=r"(r[1]), "=r"(r[2]), "=r"(r[3]) : "r"(addr));
}
static __device__ __forceinline__ void mma16816(float* c, const uint32_t* a, const uint32_t* b) {
    asm volatile(
        "mma.sync.aligned.m16n8k16.row.col.f32.f16.f16.f32 "
        "{%0,%1,%2,%3}, {%4,%5,%6,%7}, {%8,%9}, {%0,%1,%2,%3};"
        : "+f"(c[0]), "+f"(c[1]), "+f"(c[2]), "+f"(c[3])
        : "r"(a[0]), "r"(a[1]), "r"(a[2]), "r"(a[3]), "r"(b[0]), "r"(b[1]));
}
static __device__ __forceinline__ uint32_t sw128(uint32_t off) {
    return off ^ ((off >> 3) & 0x70);
}

// Stage (32KB): A @0 (16KB), B @16KB. 128 rows x 128B, SW128 swizzle.
#define STAGE_BYTES 32768
#define NSTAGE      3
#define SMEM_BYTES  (1024 + NSTAGE * STAGE_BYTES)

static __device__ __forceinline__ void load_chunk(
    const __half* A, const __half* B, int Kst,
    int m0, int n0, int koff, uint32_t stage, int tid)
{
    #pragma unroll
    for (int j = 0; j < 4; j++) {
        int id = tid + j * 256;                 // 0..1023
        int r  = id >> 3;                       // 0..127
        int cb = (id & 7) << 4;                 // byte col in 128B row
        uint32_t sw = sw128((uint32_t)((r << 7) + cb));
        cp16(stage +         sw, A + (long)(m0 + r) * Kst + koff + (cb >> 1));
        cp16(stage + 16384 + sw, B + (long)(n0 + r) * Kst + koff + (cb >> 1));
    }
    cp_commit();
}

// Shared prolog + pipelined mainloop + accumulator->tile spill (R11 engine).
// Kst = row stride of A/B; Klen = contraction length for this CTA.
#define GEMM_BODY2(Aptr, Bptr, Kst, Klen)                                        \
    extern __shared__ char smraw[];                                              \
    const int tid = threadIdx.x;                                                 \
    const int wid = tid >> 5;                                                    \
    const int lid = tid & 31;                                                    \
    const int z   = blockIdx.z;                                                  \
    const int m0  = blockIdx.y * TILE;                                           \
    const int n0  = blockIdx.x * TILE;                                           \
    const uint32_t smb = (smem_u32(smraw) + 1023u) & ~1023u;                     \
    uint32_t stg[NSTAGE];                                                        \
    _Pragma("unroll")                                                            \
    for (int s = 0; s < NSTAGE; s++) stg[s] = smb + s * STAGE_BYTES;             \
    const int wm = (wid >> 2) * 64;                                              \
    const int wn = (wid & 3) * 32;                                               \
    const int aRow  = wm + (lid & 15);                                           \
    const int aColB = (lid >> 4) << 4;                                           \
    const int bRow  = wn + (((lid >> 4) & 1) << 3) + (lid & 7);                  \
    const int bColB = ((lid >> 3) & 1) << 4;                                     \
    uint32_t aOff[4], bOff[2];                                                   \
    _Pragma("unroll")                                                            \
    for (int t = 0; t < 4; t++)                                                  \
        aOff[t] = sw128((uint32_t)((aRow + t * 16) << 7) + aColB);               \
    _Pragma("unroll")                                                            \
    for (int t = 0; t < 2; t++)                                                  \
        bOff[t] = sw128((uint32_t)((bRow + t * 16) << 7) + bColB) + 16384;       \
    float acc[4][4][4];                                                          \
    _Pragma("unroll")                                                            \
    for (int mi = 0; mi < 4; mi++)                                               \
        _Pragma("unroll")                                                        \
        for (int ni = 0; ni < 4; ni++)                                           \
            _Pragma("unroll")                                                    \
            for (int r = 0; r < 4; r++) acc[mi][ni][r] = 0.0f;                   \
    uint32_t fa[2][4], fb[2][8];                                                 \
    const int NC = (Klen) / KC;                                                  \
    load_chunk((Aptr), (Bptr), (Kst), m0, n0, 0, stg[0], tid);                   \
    load_chunk((Aptr), (Bptr), (Kst), m0, n0, KC, stg[1], tid);                  \
    uint32_t cur = stg[0];                                                       \
    int nxt = 2;                                                                 \
    for (int i = 0; i < NC; i++) {                                               \
        asm volatile("cp.async.wait_group 1;" ::: "memory");                     \
        __syncthreads();                                                         \
        if (i + 2 < NC)                                                          \
            load_chunk((Aptr), (Bptr), (Kst), m0, n0, (i + 2) * KC, stg[nxt], tid); \
        else                                                                     \
            cp_commit();                                                         \
        ldsm4(&fb[0][0], cur + bOff[0]);                                         \
        ldsm4(&fb[0][4], cur + bOff[1]);                                         \
        ldsm4(fa[0],     cur + aOff[0]);                                         \
        _Pragma("unroll")                                                        \
        for (int kk = 0; kk < 4; kk++) {                                         \
            const uint32_t xc = (uint32_t)(kk << 5);                             \
            const uint32_t xn = (uint32_t)((kk + 1) << 5);                       \
            _Pragma("unroll")                                                    \
            for (int mi = 0; mi < 4; mi++) {                                     \
                const int p  = (kk * 4 + mi) & 1;                                \
                const int np = p ^ 1;                                            \
                if (mi < 3) {                                                    \
                    ldsm4(fa[np], cur + (aOff[mi + 1] ^ xc));                     \
                } else if (kk < 3) {                                             \
                    ldsm4(&fb[(kk + 1) & 1][0], cur + (bOff[0] ^ xn));           \
                    ldsm4(&fb[(kk + 1) & 1][4], cur + (bOff[1] ^ xn));           \
                    ldsm4(fa[np], cur + (aOff[0] ^ xn));                         \
                }                                                                \
                uint32_t* B = fb[kk & 1];                                        \
                mma16816(acc[mi][0], fa[p], B + 0);                              \
                mma16816(acc[mi][1], fa[p], B + 2);                              \
                mma16816(acc[mi][2], fa[p], B + 4);                              \
                mma16816(acc[mi][3], fa[p], B + 6);                              \
            }                                                                    \
        }                                                                        \
        cur = stg[(i + 1) % NSTAGE];                                             \
        nxt = (nxt + 1) % NSTAGE;                                                \
    }                                                                            \
    __syncthreads();                                                             \
    float* tile = (float*)(smraw + (smb - smem_u32(smraw)));                     \
    {                                                                            \
        const int r0 = lid >> 2;                                                 \
        const int c0 = (lid & 3) * 2;                                            \
        _Pragma("unroll")                                                        \
        for (int mi = 0; mi < 4; mi++)                                           \
            _Pragma("unroll")                                                    \
            for (int ni = 0; ni < 4; ni++) {                                     \
                int m = wm + mi * 16 + r0;                                       \
                int n = wn + ni * 8 + c0;                                        \
                tile[m * 129 + n]           = acc[mi][ni][0];                    \
                tile[m * 129 + n + 1]       = acc[mi][ni][1];                    \
                tile[(m + 8) * 129 + n]     = acc[mi][ni][2];                    \
                tile[(m + 8) * 129 + n + 1] = acc[mi][ni][3];                    \
            }                                                                    \
    }                                                                            \
    __syncthreads();

#define GEMM_BODY(Aptr, Bptr, Kdim) GEMM_BODY2(Aptr, Bptr, Kdim, Kdim)

// ---------------- M = Wq Wk^T split-K: fp32 transposed partials -------------
__global__ void __launch_bounds__(256, 2)
gemm_wm(const __half* __restrict__ Wq, const __half* __restrict__ Wk,
        float* __restrict__ Mpart)
{
    GEMM_BODY2(Wq + blockIdx.z * WMKLEN, Wk + blockIdx.z * WMKLEN, DIM, WMKLEN)
    float* dst = Mpart + (long)z * DIM * DIM;
    for (int idx = tid; idx < TILE * TILE; idx += 256) {
        int n = idx >> 7, mm = idx & 127;
        dst[(long)(n0 + n) * DIM + m0 + mm] = tile[mm * 129 + n];
    }
}

// ---------------- reduce split-K partials -> fp16 Mt ------------------------
__global__ void __launch_bounds__(256)
reduce_m(const float* __restrict__ Mpart, __half* __restrict__ Mt)
{
    int i = blockIdx.x * 256 + threadIdx.x;      // float4 index, DIM*DIM/4 total
    const float4* p = (const float4*)Mpart;
    const int st = DIM * DIM / 4;
    float4 a = p[i], b = p[i + st], c = p[i + 2 * st], d = p[i + 3 * st];
    float4 s;
    s.x = a.x + b.x + c.x + d.x;
    s.y = a.y + b.y + c.y + d.y;
    s.z = a.z + b.z + c.z + d.z;
    s.w = a.w + b.w + c.w + d.w;
    __half2* o = (__half2*)Mt;
    o[i * 2]     = __floats2half2_rn(s.x, s.y);
    o[i * 2 + 1] = __floats2half2_rn(s.z, s.w);
}

// ---------------- proj: z=0: G = x M (plain); z=1: Vt = (x Wv + bv)^T -------
__global__ void __launch_bounds__(256, 2)
gemm_proj(const __half* __restrict__ A, const __half* __restrict__ Bmt,
          const __half* __restrict__ Bwv, const float* __restrict__ bv,
          __half* __restrict__ oG, __half* __restrict__ oVt)
{
    GEMM_BODY(A, (blockIdx.z == 0 ? Bmt : Bwv), DIM)

    if (z == 0) {
        for (int idx = tid; idx < TILE * TILE; idx += 256) {
            int r = idx >> 7, c = idx & 127;
            oG[(long)(m0 + r) * DKV + n0 + c] = __float2half(tile[r * 129 + c]);
        }
    } else {
        const int b = m0 >> 11, seq0 = m0 & 2047;
        for (int idx = tid; idx < TILE * TILE; idx += 256) {
            int n = idx >> 7, mm = idx & 127;
            float v = tile[mm * 129 + n] + bv[n0 + n];
            oVt[(long)b * DKV * SEQ + (long)(n0 + n) * SEQ + seq0 + mm] = __float2half(v);
        }
    }
}

// ---------------- scores: E = exp((G x^T + t[p]) / 32 + mask) fp16 ----------
__global__ void __launch_bounds__(256, 2)
gemm_scores(const __half* __restrict__ G, const __half* __restrict__ X,
            const float* __restrict__ mask, const float* __restrict__ tv,
            __half* __restrict__ Eh, float* __restrict__ rsum)
{
    GEMM_BODY(G + (long)blockIdx.z * SEQ * DKV,
              X + (long)blockIdx.z * SEQ * DIM, DIM)

    const long bo = (long)z * SEQ * SEQ;
    for (int idx = tid; idx < TILE * TILE; idx += 256) {
        int r = idx >> 7, c = idx & 127;
        long o = bo + (long)(m0 + r) * SEQ + n0 + c;
        float s = tile[r * 129 + c] + tv[(z << 11) + n0 + c];
        float e = __expf(__fmaf_rn(s, 0.03125f, mask[o]));
        __half eh = __float2half(e);
        Eh[o] = eh;
        tile[r * 129 + c] = __half2float(eh);
    }
    __syncthreads();
    if (tid < 128) {
        float s = 0.0f;
        #pragma unroll 8
        for (int c = 0; c < 128; c++) s += tile[tid * 129 + c];
        rsum[((long)(z << 11) + m0 + tid) * 16 + blockIdx.x] = s;
    }
}

// ---------------- AV GEMM: out = inv[row] * (E @ V); inv from rsum ----------
__global__ void __launch_bounds__(256, 2)
gemm_av(const __half* __restrict__ E, const __half* __restrict__ Vt,
        const float* __restrict__ rsum, float* __restrict__ outF)
{
    GEMM_BODY(E + (long)blockIdx.z * SEQ * SEQ,
              Vt + (long)blockIdx.z * DKV * SEQ, SEQ)

    // per-row 1/sum computed locally from the 16 rsum partials (L2-hot)
    float* sinv = tile + 128 * 129;
    if (tid < 128) {
        const float* rs = rsum + ((long)((z << 11) + m0 + tid)) * 16;
        float s = 0.0f;
        #pragma unroll
        for (int t = 0; t < 16; t++) s += rs[t];
        sinv[tid] = 1.0f / s;
    }
    __syncthreads();

    const long bo = (long)z * SEQ * DKV;
    for (int idx = tid; idx < TILE * TILE; idx += 256) {
        int r = idx >> 7, c = idx & 127;
        outF[bo + (long)(m0 + r) * DKV + n0 + c] = tile[r * 129 + c] * sinv[r];
    }
}

// ---------------- fused: x -> fp16 + t[row] = x_row . wt --------------------
__global__ void __launch_bounds__(256)
conv_x_t(const float* __restrict__ x, const float* __restrict__ wt,
         __half* __restrict__ x16, float* __restrict__ tOut)
{
    __shared__ float red[256];
    const int row = blockIdx.x;
    const int t = threadIdx.x;
    float4 v = ((const float4*)(x + (long)row * DIM))[t];
    float4 w = ((const float4*)wt)[t];
    __half2* o2 = (__half2*)(x16 + (long)row * DIM);
    o2[t * 2]     = __floats2half2_rn(v.x, v.y);
    o2[t * 2 + 1] = __floats2half2_rn(v.z, v.w);
    red[t] = v.x * w.x + v.y * w.y + v.z * w.z + v.w * w.w;
    __syncthreads();
    #pragma unroll
    for (int k = 128; k > 0; k >>= 1) {
        if (t < k) red[t] += red[t + k];
        __syncthreads();
    }
    if (t == 0) tOut[row] = red[0];
}

// ---------------- fused: Wq/Wk -> fp16 + wt = Wk bq -------------------------
__global__ void __launch_bounds__(256)
convw_dot(const float* __restrict__ Wq, const float* __restrict__ Wk,
          const float* __restrict__ bq,
          __half* __restrict__ oq, __half* __restrict__ ok,
          float* __restrict__ wt)
{
    __shared__ float red[256];
    const int d = blockIdx.x;
    const int t = threadIdx.x;
    const float* W = blockIdx.y ? Wk : Wq;
    __half* o      = blockIdx.y ? ok : oq;

    float4 v = ((const float4*)(W + (long)d * DKV))[t];
    __half2* o2 = (__half2*)(o + (long)d * DKV);
    o2[t * 2]     = __floats2half2_rn(v.x, v.y);
    o2[t * 2 + 1] = __floats2half2_rn(v.z, v.w);

    if (blockIdx.y) {
        float4 b = ((const float4*)bq)[t];
        red[t] = v.x * b.x + v.y * b.y + v.z * b.z + v.w * b.w;
        __syncthreads();
        #pragma unroll
        for (int k = 128; k > 0; k >>= 1) {
            if (t < k) red[t] += red[t + k];
            __syncthreads();
        }
        if (t == 0) wt[d] = red[0];
    }
}

// ---------------- transpose + convert Wv ------------------------------------
__global__ void __launch_bounds__(256)
tconv_wv(const float* __restrict__ in, __half* __restrict__ out)
{
    __shared__ float t[32][33];
    const int bx = blockIdx.x * 32, by = blockIdx.y * 32;
    const int tx = threadIdx.x, ty = threadIdx.y;       // block (32,8)
    #pragma unroll
    for (int k = 0; k < 32; k += 8)
        t[ty + k][tx] = in[(long)(by + ty + k) * DKV + bx + tx];
    __syncthreads();
    #pragma unroll
    for (int k = 0; k < 32; k += 8)
        out[(long)(bx + ty + k) * DIM + by + tx] = __float2half(t[tx][ty + k]);
}

// ---------------------------------------------------------------------------
extern "C" void kernel_launch(void* const* d_in, const int* in_sizes, int n_in,
                              void* d_out, int out_size)
{
    const float* x    = (const float*)d_in[0];
    const float* mask = (const float*)d_in[1];
    const float* Wq   = (const float*)d_in[2];
    const float* bq   = (const float*)d_in[3];
    const float* Wk   = (const float*)d_in[4];
    const float* bk   = (const float*)d_in[5];
    const float* Wv   = (const float*)d_in[6];
    const float* bv   = (const float*)d_in[7];
    float* out = (float*)d_out;
    (void)bk;   // cancels in softmax (u[q], c terms)

    __half *x16, *wq16, *wk16, *wvt16, *mt16, *g16, *vt16, *Ep;
    float *rsp, *wtp, *tp, *mpp;
    cudaGetSymbolAddress((void**)&x16,   g_x16);
    cudaGetSymbolAddress((void**)&wq16,  g_wq16);
    cudaGetSymbolAddress((void**)&wk16,  g_wk16);
    cudaGetSymbolAddress((void**)&wvt16, g_wvt16);
    cudaGetSymbolAddress((void**)&mt16,  g_mt16);
    cudaGetSymbolAddress((void**)&mpp,   g_mpart);
    cudaGetSymbolAddress((void**)&g16,   g_g16);
    cudaGetSymbolAddress((void**)&vt16,  g_vt16);
    cudaGetSymbolAddress((void**)&Ep,    g_E);
    cudaGetSymbolAddress((void**)&rsp,   g_rsum);
    cudaGetSymbolAddress((void**)&wtp,   g_wt);
    cudaGetSymbolAddress((void**)&tp,    g_t);

    cudaFuncSetAttribute(gemm_wm,     cudaFuncAttributeMaxDynamicSharedMemorySize, SMEM_BYTES);
    cudaFuncSetAttribute(gemm_proj,   cudaFuncAttributeMaxDynamicSharedMemorySize, SMEM_BYTES);
    cudaFuncSetAttribute(gemm_scores, cudaFuncAttributeMaxDynamicSharedMemorySize, SMEM_BYTES);
    cudaFuncSetAttribute(gemm_av,     cudaFuncAttributeMaxDynamicSharedMemorySize, SMEM_BYTES);

    // 1) weight conversion + wt = Wk bq; x conversion fused with t = x wt
    {
        dim3 gw(DIM, 2);
        convw_dot<<<gw, 256>>>(Wq, Wk, bq, wq16, wk16, wtp);
        dim3 tb(32, 8), tg(32, 32);
        tconv_wv<<<tg, tb>>>(Wv, wvt16);
        conv_x_t<<<MTOT, 256>>>(x, wtp, x16, tp);
    }

    dim3 blk(256);

    // 2) M = Wq Wk^T via split-K (fp32 transposed partials), then reduce
    {
        dim3 g(DIM / TILE, DIM / TILE, WMSPLIT);
        gemm_wm<<<g, blk, SMEM_BYTES>>>(wq16, wk16, mpp);
        reduce_m<<<DIM * DIM / 4 / 256, 256>>>(mpp, mt16);
    }

    // 3) z=0: G = x M;  z=1: Vt = (x Wv + bv)^T
    {
        dim3 g(DKV / TILE, MTOT / TILE, 2);
        gemm_proj<<<g, blk, SMEM_BYTES>>>(x16, mt16, wvt16, bv, g16, vt16);
    }

    // 4) E = exp((G x^T + t)/32 + mask) fp16, per-tile row sums
    {
        dim3 g(SEQ / TILE, SEQ / TILE, BATCH);
        gemm_scores<<<g, blk, SMEM_BYTES>>>(g16, x16, mask, tp, Ep, rsp);
    }

    // 5) out = inv * (E @ V), inv folded into epilogue
    {
        dim3 g(DKV / TILE, SEQ / TILE, BATCH);
        gemm_av<<<g, blk, SMEM_BYTES>>>(Ep, vt16, rsp, out);
    }
}